// round 2
// baseline (speedup 1.0000x reference)
#include <cuda_runtime.h>
#include <math_constants.h>
#include <cstdint>

#define BATCH 8
#define NPTS  4096
#define KNN   20
#define CIN   26      // 2*D + K
#define C1    64
#define C2    64
#define C3    128
#define C4    256
#define CCAT  512
#define EMB   512

// Scratch (device globals: sanctioned, no runtime allocation)
__device__ int   g_idx[BATCH * NPTS * KNN];                 // 2.6 MB
__device__ float g_cat[(size_t)BATCH * NPTS * CCAT];        // 64 MB

// ---------------------------------------------------------------------------
// Kernel 1: exact 20-NN per point.
// Rank key v = sq_m - 2*x_n.x_m  (ascending v == descending reference "pair").
// Ties broken by lower index (strict-less insertion while scanning m ascending)
// which matches jax.lax.top_k tie-breaking.
// ---------------------------------------------------------------------------
__global__ __launch_bounds__(128) void knn_kernel(const float* __restrict__ x) {
    extern __shared__ float4 xs[];   // 4096 * 16B = 64KB
    const int b = blockIdx.y;
    const float* xb = x + (size_t)b * 3 * NPTS;

    for (int m = threadIdx.x; m < NPTS; m += blockDim.x) {
        float x0 = xb[m], x1 = xb[NPTS + m], x2 = xb[2 * NPTS + m];
        float sq = fmaf(x0, x0, fmaf(x1, x1, x2 * x2));
        xs[m] = make_float4(x0, x1, x2, sq);
    }
    __syncthreads();

    const int n = blockIdx.x * blockDim.x + threadIdx.x;
    float4 p = xs[n];
    const float a0 = -2.0f * p.x, a1 = -2.0f * p.y, a2 = -2.0f * p.z;

    float bv[KNN];
    int   bi[KNN];
#pragma unroll
    for (int t = 0; t < KNN; ++t) { bv[t] = CUDART_INF_F; bi[t] = -1; }

#pragma unroll 4
    for (int m = 0; m < NPTS; ++m) {
        float4 q = xs[m];
        float v = fmaf(a0, q.x, fmaf(a1, q.y, fmaf(a2, q.z, q.w)));
        if (v < bv[KNN - 1]) {
            bool ins = true;
#pragma unroll
            for (int t = KNN - 1; t >= 1; --t) {
                bool shift = v < bv[t - 1];
                if (shift)      { bv[t] = bv[t - 1]; bi[t] = bi[t - 1]; }
                else if (ins)   { bv[t] = v;         bi[t] = m; }
                ins = shift;
            }
            if (ins) { bv[0] = v; bi[0] = m; }
        }
    }

    int* outp = g_idx + ((size_t)b * NPTS + n) * KNN;
#pragma unroll
    for (int t = 0; t < KNN; ++t) outp[t] = bi[t];
}

// ---------------------------------------------------------------------------
// Kernel 2: fused graph-feature + 4 conv layers + per-k max -> cat (32768x512)
// All weights transposed into smem ([c][o] layout), 1 block/SM, 512 threads.
// ---------------------------------------------------------------------------
#define PTS_PER_BLK 16

__global__ __launch_bounds__(512, 1) void mlp_kernel(
    const float* __restrict__ x,
    const float* __restrict__ w1, const float* __restrict__ w2,
    const float* __restrict__ w3, const float* __restrict__ w4) {

    extern __shared__ float sm[];
    float* W1t   = sm;                    // 26*64   = 1664
    float* W2t   = W1t + CIN * C1;        // 64*64   = 4096
    float* W3t   = W2t + C2 * C2;         // 64*128  = 8192
    float* W4t   = W3t + C2 * C3;         // 128*256 = 32768
    float* h1    = W4t + C3 * C4;         // 20*64
    float* h2    = h1 + KNN * C1;         // 20*64   (reused as partial-max)
    float* h3    = h2 + KNN * C2;         // 20*128
    float* s_nbr = h3 + KNN * C3;         // 20*4
    float* s_dist= s_nbr + KNN * 4;       // 20
    float* s_base= s_dist + KNN;          // 64
    float* s_cat = s_base + C1;           // 512
    float* s_xn  = s_cat + CCAT;          // 4

    const int tid = threadIdx.x;

    // -- stage transposed weights into smem (coalesced gmem reads) --
    for (int i = tid; i < C1 * CIN; i += 512) { int o = i / CIN, c = i % CIN; W1t[c * C1 + o] = w1[i]; }
    for (int i = tid; i < C2 * C2;  i += 512) { int o = i >> 6,  c = i & 63;  W2t[c * C2 + o] = w2[i]; }
    for (int i = tid; i < C3 * C2;  i += 512) { int o = i >> 6,  c = i & 63;  W3t[c * C3 + o] = w3[i]; }
    for (int i = tid; i < C4 * C3;  i += 512) { int o = i >> 7,  c = i & 127; W4t[c * C4 + o] = w4[i]; }
    __syncthreads();

    for (int pp = 0; pp < PTS_PER_BLK; ++pp) {
        const int pt = blockIdx.x * PTS_PER_BLK + pp;
        const int b  = pt >> 12;
        const int n  = pt & (NPTS - 1);
        const float* xb = x + (size_t)b * 3 * NPTS;

        // ---- stage A: gather neighbors, dist ----
        if (tid < 3) s_xn[tid] = xb[tid * NPTS + n];
        if (tid < KNN) {
            int nb = g_idx[((size_t)b * NPTS + n) * KNN + tid];
            float c0 = xb[n], c1 = xb[NPTS + n], c2 = xb[2 * NPTS + n];
            float n0 = xb[nb], n1 = xb[NPTS + nb], n2 = xb[2 * NPTS + nb];
            s_nbr[tid * 4 + 0] = n0;
            s_nbr[tid * 4 + 1] = n1;
            s_nbr[tid * 4 + 2] = n2;
            float d0 = n0 - c0, d1 = n1 - c1, d2 = n2 - c2;
            s_dist[tid] = sqrtf(fmaf(d0, d0, fmaf(d1, d1, d2 * d2)) + 1e-12f);
        }
        __syncthreads();

        // ---- stage B: layer-1 constant part (xc + distr columns) ----
        if (tid < C1) {
            float acc = 0.0f;
#pragma unroll
            for (int d = 0; d < 3; ++d) acc = fmaf(W1t[d * C1 + tid], s_xn[d], acc);
#pragma unroll
            for (int j = 0; j < KNN; ++j) acc = fmaf(W1t[(6 + j) * C1 + tid], s_dist[j], acc);
            s_base[tid] = acc;
        }
        __syncthreads();

        // ---- layer 1: h1[k][o] = relu(base[o] + W1[:,3:6].nbr_k) ----
        {
            int o = tid & 63, g = tid >> 6;          // g in 0..7
            float wa = W1t[3 * C1 + o], wb = W1t[4 * C1 + o], wc = W1t[5 * C1 + o];
            float base = s_base[o];
#pragma unroll
            for (int j = 0; j < 3; ++j) {
                int k = g + 8 * j;
                if (j < 2 || g < 4) {
                    float v = fmaf(wa, s_nbr[k * 4 + 0],
                              fmaf(wb, s_nbr[k * 4 + 1],
                              fmaf(wc, s_nbr[k * 4 + 2], base)));
                    h1[k * C1 + o] = fmaxf(v, 0.0f);
                }
            }
        }
        __syncthreads();

        // ---- layer 2: 64 -> 64 ----
        {
            int o = tid & 63, g = tid >> 6;          // k = g, g+8, g+16(g<4)
            float a0 = 0.f, a1 = 0.f, a2 = 0.f;
#pragma unroll
            for (int c = 0; c < C2; c += 4) {
                float w0 = W2t[(c + 0) * C2 + o];
                float wA = W2t[(c + 1) * C2 + o];
                float wB = W2t[(c + 2) * C2 + o];
                float wC = W2t[(c + 3) * C2 + o];
                float4 hA = *(const float4*)(h1 + (g)      * C1 + c);
                float4 hB = *(const float4*)(h1 + (g + 8)  * C1 + c);
                a0 = fmaf(w0, hA.x, fmaf(wA, hA.y, fmaf(wB, hA.z, fmaf(wC, hA.w, a0))));
                a1 = fmaf(w0, hB.x, fmaf(wA, hB.y, fmaf(wB, hB.z, fmaf(wC, hB.w, a1))));
                if (g < 4) {
                    float4 hC = *(const float4*)(h1 + (g + 16) * C1 + c);
                    a2 = fmaf(w0, hC.x, fmaf(wA, hC.y, fmaf(wB, hC.z, fmaf(wC, hC.w, a2))));
                }
            }
            h2[(g)      * C2 + o] = fmaxf(a0, 0.f);
            h2[(g + 8)  * C2 + o] = fmaxf(a1, 0.f);
            if (g < 4) h2[(g + 16) * C2 + o] = fmaxf(a2, 0.f);
        }
        __syncthreads();

        // ---- layer 3: 64 -> 128 ----
        {
            int o = tid & 127, g = tid >> 7;         // g in 0..3, k = g + 4j
            float acc[5] = {0.f, 0.f, 0.f, 0.f, 0.f};
#pragma unroll
            for (int c = 0; c < C2; c += 4) {
                float w0 = W3t[(c + 0) * C3 + o];
                float wA = W3t[(c + 1) * C3 + o];
                float wB = W3t[(c + 2) * C3 + o];
                float wC = W3t[(c + 3) * C3 + o];
#pragma unroll
                for (int j = 0; j < 5; ++j) {
                    float4 h = *(const float4*)(h2 + (g + 4 * j) * C2 + c);
                    acc[j] = fmaf(w0, h.x, fmaf(wA, h.y, fmaf(wB, h.z, fmaf(wC, h.w, acc[j]))));
                }
            }
#pragma unroll
            for (int j = 0; j < 5; ++j)
                h3[(g + 4 * j) * C3 + o] = fmaxf(acc[j], 0.f);
        }
        __syncthreads();

        // ---- layer 4: 128 -> 256 (accumulate in regs, fuse max) ----
        float acc4[10];
        {
#pragma unroll
            for (int j = 0; j < 10; ++j) acc4[j] = 0.f;
            int o = tid & 255, g = tid >> 8;         // g in 0..1, k = g + 2j
#pragma unroll 8
            for (int c = 0; c < C3; c += 4) {
                float w0 = W4t[(c + 0) * C4 + o];
                float wA = W4t[(c + 1) * C4 + o];
                float wB = W4t[(c + 2) * C4 + o];
                float wC = W4t[(c + 3) * C4 + o];
#pragma unroll
                for (int j = 0; j < 10; ++j) {
                    float4 h = *(const float4*)(h3 + (g + 2 * j) * C3 + c);
                    acc4[j] = fmaf(w0, h.x, fmaf(wA, h.y, fmaf(wB, h.z, fmaf(wC, h.w, acc4[j]))));
                }
            }
        }

        // ---- maxes x1..x3 (reads of h1..h3 only) ----
        if (tid < 64) {
            float m = 0.f;
#pragma unroll
            for (int k = 0; k < KNN; ++k) m = fmaxf(m, h1[k * C1 + tid]);
            s_cat[tid] = m;
        } else if (tid < 128) {
            int o = tid - 64; float m = 0.f;
#pragma unroll
            for (int k = 0; k < KNN; ++k) m = fmaxf(m, h2[k * C2 + o]);
            s_cat[64 + o] = m;
        } else if (tid < 256) {
            int o = tid - 128; float m = 0.f;
#pragma unroll
            for (int k = 0; k < KNN; ++k) m = fmaxf(m, h3[k * C3 + o]);
            s_cat[128 + o] = m;
        }
        __syncthreads();   // h2 reads done -> safe to reuse as partial-max

        {
            int o = tid & 255, g = tid >> 8;
            float pm = 0.f;   // relu folded: max(relu(a)) = max(0, max a)
#pragma unroll
            for (int j = 0; j < 10; ++j) pm = fmaxf(pm, acc4[j]);
            h2[g * 256 + o] = pm;
        }
        __syncthreads();
        if (tid < 256) s_cat[256 + tid] = fmaxf(h2[tid], h2[256 + tid]);
        __syncthreads();

        g_cat[(size_t)pt * CCAT + tid] = s_cat[tid];
        __syncthreads();   // protect smem before next point
    }
}

// ---------------------------------------------------------------------------
// Kernel 3: out[b][o][n] = relu(sum_c w5[o][c] * cat[b][n][c])
// 64x64 tile, 256 threads, 4x4 micro-tile.
// ---------------------------------------------------------------------------
__global__ __launch_bounds__(256) void gemm5_kernel(const float* __restrict__ w5,
                                                    float* __restrict__ out) {
    __shared__ __align__(16) float As[16][68];   // w5 chunk  [c][o]
    __shared__ __align__(16) float Bs[16][68];   // cat chunk [c][n]

    const int b  = blockIdx.z;
    const int o0 = blockIdx.y * 64;
    const int n0 = blockIdx.x * 64;
    const float* cat = g_cat + (size_t)b * NPTS * CCAT;

    const int tx = threadIdx.x & 15;
    const int ty = threadIdx.x >> 4;

    float acc[4][4];
#pragma unroll
    for (int i = 0; i < 4; ++i)
#pragma unroll
        for (int j = 0; j < 4; ++j) acc[i][j] = 0.f;

    const int lrow = threadIdx.x >> 2;          // 0..63
    const int lcc  = (threadIdx.x & 3) * 4;     // 0,4,8,12

    for (int c0 = 0; c0 < CCAT; c0 += 16) {
        float4 av = *(const float4*)(w5 + (size_t)(o0 + lrow) * CCAT + c0 + lcc);
        float4 bv = *(const float4*)(cat + (size_t)(n0 + lrow) * CCAT + c0 + lcc);
        As[lcc + 0][lrow] = av.x; As[lcc + 1][lrow] = av.y;
        As[lcc + 2][lrow] = av.z; As[lcc + 3][lrow] = av.w;
        Bs[lcc + 0][lrow] = bv.x; Bs[lcc + 1][lrow] = bv.y;
        Bs[lcc + 2][lrow] = bv.z; Bs[lcc + 3][lrow] = bv.w;
        __syncthreads();

#pragma unroll
        for (int c = 0; c < 16; ++c) {
            float4 a = *(const float4*)(&As[c][ty * 4]);
            float4 bb = *(const float4*)(&Bs[c][tx * 4]);
            acc[0][0] = fmaf(a.x, bb.x, acc[0][0]); acc[0][1] = fmaf(a.x, bb.y, acc[0][1]);
            acc[0][2] = fmaf(a.x, bb.z, acc[0][2]); acc[0][3] = fmaf(a.x, bb.w, acc[0][3]);
            acc[1][0] = fmaf(a.y, bb.x, acc[1][0]); acc[1][1] = fmaf(a.y, bb.y, acc[1][1]);
            acc[1][2] = fmaf(a.y, bb.z, acc[1][2]); acc[1][3] = fmaf(a.y, bb.w, acc[1][3]);
            acc[2][0] = fmaf(a.z, bb.x, acc[2][0]); acc[2][1] = fmaf(a.z, bb.y, acc[2][1]);
            acc[2][2] = fmaf(a.z, bb.z, acc[2][2]); acc[2][3] = fmaf(a.z, bb.w, acc[2][3]);
            acc[3][0] = fmaf(a.w, bb.x, acc[3][0]); acc[3][1] = fmaf(a.w, bb.y, acc[3][1]);
            acc[3][2] = fmaf(a.w, bb.z, acc[3][2]); acc[3][3] = fmaf(a.w, bb.w, acc[3][3]);
        }
        __syncthreads();
    }

#pragma unroll
    for (int i = 0; i < 4; ++i) {
        int o = o0 + ty * 4 + i;
        float4 r;
        r.x = fmaxf(acc[i][0], 0.f); r.y = fmaxf(acc[i][1], 0.f);
        r.z = fmaxf(acc[i][2], 0.f); r.w = fmaxf(acc[i][3], 0.f);
        *(float4*)(out + ((size_t)b * EMB + o) * NPTS + n0 + tx * 4) = r;
    }
}

// ---------------------------------------------------------------------------
extern "C" void kernel_launch(void* const* d_in, const int* in_sizes, int n_in,
                              void* d_out, int out_size) {
    const float* x  = (const float*)d_in[0];
    const float* w1 = (const float*)d_in[1];
    const float* w2 = (const float*)d_in[2];
    const float* w3 = (const float*)d_in[3];
    const float* w4 = (const float*)d_in[4];
    const float* w5 = (const float*)d_in[5];
    float* out = (float*)d_out;

    const int knn_smem = NPTS * sizeof(float4);                 // 64 KB
    const int mlp_smem = (CIN * C1 + C2 * C2 + C2 * C3 + C3 * C4 +
                          KNN * C1 + KNN * C2 + KNN * C3 +
                          KNN * 4 + KNN + C1 + CCAT + 4) * sizeof(float);  // ~210 KB

    cudaFuncSetAttribute(knn_kernel, cudaFuncAttributeMaxDynamicSharedMemorySize, knn_smem);
    cudaFuncSetAttribute(mlp_kernel, cudaFuncAttributeMaxDynamicSharedMemorySize, mlp_smem);

    knn_kernel<<<dim3(NPTS / 128, BATCH), 128, knn_smem>>>(x);
    mlp_kernel<<<(BATCH * NPTS) / PTS_PER_BLK, 512, mlp_smem>>>(x, w1, w2, w3, w4);
    gemm5_kernel<<<dim3(NPTS / 64, EMB / 64, BATCH), 256>>>(w5, out);
}

// round 4
// speedup vs baseline: 1.1595x; 1.1595x over previous
#include <cuda_runtime.h>
#include <math_constants.h>
#include <mma.h>
#include <cstdint>

using namespace nvcuda;

#define BATCH 8
#define NPTS  4096
#define KNN   20
#define CIN   26
#define C1    64
#define C2    64
#define C3    128
#define C4    256
#define CCAT  512
#define EMB   512

__device__ int   g_idx[BATCH * NPTS * KNN];
__device__ float g_cat[(size_t)BATCH * NPTS * CCAT];     // 64 MB
__device__ float g_h2[(size_t)BATCH * NPTS * KNN * C2];  // 168 MB

__device__ __forceinline__ float rna_tf32(float x) {
    uint32_t o;
    asm("cvt.rna.tf32.f32 %0, %1;" : "=r"(o) : "r"(__float_as_uint(x)));
    return __uint_as_float(o);
}

// ===================== Kernel 1: exact 20-NN =====================
__global__ __launch_bounds__(256) void knn_kernel(const float* __restrict__ x) {
    extern __shared__ float4 xs[];   // 4096 * 16B = 64KB
    const int b = blockIdx.y;
    const float* xb = x + (size_t)b * 3 * NPTS;
    for (int m = threadIdx.x; m < NPTS; m += blockDim.x) {
        float x0 = xb[m], x1 = xb[NPTS + m], x2 = xb[2 * NPTS + m];
        xs[m] = make_float4(x0, x1, x2, fmaf(x0, x0, fmaf(x1, x1, x2 * x2)));
    }
    __syncthreads();
    const int n = blockIdx.x * blockDim.x + threadIdx.x;
    float4 p = xs[n];
    const float a0 = -2.f * p.x, a1 = -2.f * p.y, a2 = -2.f * p.z;
    float bv[KNN]; int bi[KNN];
#pragma unroll
    for (int t = 0; t < KNN; ++t) { bv[t] = CUDART_INF_F; bi[t] = -1; }
#pragma unroll 4
    for (int m = 0; m < NPTS; ++m) {
        float4 q = xs[m];
        float v = fmaf(a0, q.x, fmaf(a1, q.y, fmaf(a2, q.z, q.w)));
        if (v < bv[KNN - 1]) {
            bool ins = true;
#pragma unroll
            for (int t = KNN - 1; t >= 1; --t) {
                bool sh = v < bv[t - 1];
                if (sh)       { bv[t] = bv[t - 1]; bi[t] = bi[t - 1]; }
                else if (ins) { bv[t] = v;         bi[t] = m; }
                ins = sh;
            }
            if (ins) { bv[0] = v; bi[0] = m; }
        }
    }
    int* outp = g_idx + ((size_t)b * NPTS + n) * KNN;
#pragma unroll
    for (int t = 0; t < KNN; ++t) outp[t] = bi[t];
}

// ===================== Kernel 2: feature + L1 + L2 (scalar) =====================
#define PTS_PER_BLK 8
__global__ __launch_bounds__(512) void l12_kernel(
    const float* __restrict__ x, const float* __restrict__ w1, const float* __restrict__ w2) {
    __shared__ float W1t[CIN * C1], W2t[C2 * C2];
    __shared__ float h1[KNN * C1], h2[KNN * C2];
    __shared__ float s_nbr[KNN * 4], s_dist[KNN], s_base[C1], s_xn[4];
    const int tid = threadIdx.x;
    for (int i = tid; i < C1 * CIN; i += 512) { int o = i / CIN, c = i % CIN; W1t[c * C1 + o] = w1[i]; }
    for (int i = tid; i < C2 * C2;  i += 512) { int o = i >> 6,  c = i & 63;  W2t[c * C2 + o] = w2[i]; }
    __syncthreads();

    for (int pp = 0; pp < PTS_PER_BLK; ++pp) {
        const int pt = blockIdx.x * PTS_PER_BLK + pp;
        const int b = pt >> 12, n = pt & (NPTS - 1);
        const float* xb = x + (size_t)b * 3 * NPTS;
        if (tid < 3) s_xn[tid] = xb[tid * NPTS + n];
        if (tid < KNN) {
            int nb = g_idx[((size_t)b * NPTS + n) * KNN + tid];
            float c0 = xb[n], c1 = xb[NPTS + n], c2 = xb[2 * NPTS + n];
            float n0 = xb[nb], n1 = xb[NPTS + nb], n2 = xb[2 * NPTS + nb];
            s_nbr[tid * 4 + 0] = n0; s_nbr[tid * 4 + 1] = n1; s_nbr[tid * 4 + 2] = n2;
            float d0 = n0 - c0, d1 = n1 - c1, d2 = n2 - c2;
            s_dist[tid] = sqrtf(fmaf(d0, d0, fmaf(d1, d1, d2 * d2)) + 1e-12f);
        }
        __syncthreads();
        if (tid < C1) {
            float acc = 0.f;
#pragma unroll
            for (int d = 0; d < 3; ++d) acc = fmaf(W1t[d * C1 + tid], s_xn[d], acc);
#pragma unroll
            for (int j = 0; j < KNN; ++j) acc = fmaf(W1t[(6 + j) * C1 + tid], s_dist[j], acc);
            s_base[tid] = acc;
        }
        __syncthreads();
        {   // layer 1
            int o = tid & 63, g = tid >> 6;
            float wa = W1t[3 * C1 + o], wb = W1t[4 * C1 + o], wc = W1t[5 * C1 + o];
            float base = s_base[o];
#pragma unroll
            for (int j = 0; j < 3; ++j) {
                int k = g + 8 * j;
                if (j < 2 || g < 4) {
                    float v = fmaf(wa, s_nbr[k * 4], fmaf(wb, s_nbr[k * 4 + 1], fmaf(wc, s_nbr[k * 4 + 2], base)));
                    h1[k * C1 + o] = fmaxf(v, 0.f);
                }
            }
        }
        __syncthreads();
        {   // layer 2 (+ spill rows)
            int o = tid & 63, g = tid >> 6;
            float a0 = 0.f, a1 = 0.f, a2 = 0.f;
#pragma unroll
            for (int c = 0; c < C2; c += 4) {
                float w0 = W2t[c * C2 + o], wA = W2t[(c + 1) * C2 + o];
                float wB = W2t[(c + 2) * C2 + o], wC = W2t[(c + 3) * C2 + o];
                float4 hA = *(const float4*)(h1 + g * C1 + c);
                float4 hB = *(const float4*)(h1 + (g + 8) * C1 + c);
                a0 = fmaf(w0, hA.x, fmaf(wA, hA.y, fmaf(wB, hA.z, fmaf(wC, hA.w, a0))));
                a1 = fmaf(w0, hB.x, fmaf(wA, hB.y, fmaf(wB, hB.z, fmaf(wC, hB.w, a1))));
                if (g < 4) {
                    float4 hC = *(const float4*)(h1 + (g + 16) * C1 + c);
                    a2 = fmaf(w0, hC.x, fmaf(wA, hC.y, fmaf(wB, hC.z, fmaf(wC, hC.w, a2))));
                }
            }
            float* hr = g_h2 + (size_t)pt * KNN * C2;
            float v0 = fmaxf(a0, 0.f); h2[g * C2 + o] = v0;        hr[g * C2 + o] = v0;
            float v1 = fmaxf(a1, 0.f); h2[(g + 8) * C2 + o] = v1;  hr[(g + 8) * C2 + o] = v1;
            if (g < 4) { float v2 = fmaxf(a2, 0.f); h2[(g + 16) * C2 + o] = v2; hr[(g + 16) * C2 + o] = v2; }
        }
        __syncthreads();
        if (tid < 64) {
            float m = 0.f;
#pragma unroll
            for (int k = 0; k < KNN; ++k) m = fmaxf(m, h1[k * C1 + tid]);
            g_cat[(size_t)pt * CCAT + tid] = m;
        } else if (tid < 128) {
            int o = tid - 64; float m = 0.f;
#pragma unroll
            for (int k = 0; k < KNN; ++k) m = fmaxf(m, h2[k * C2 + o]);
            g_cat[(size_t)pt * CCAT + 64 + o] = m;
        }
        __syncthreads();
    }
}

// ===================== Kernel 3: L3+L4 via wmma tf32 =====================
// Block = 8 points = 160 rows. 256 threads (8 warps).
// smem: h2s[160][72], h3s[160][136], wbuf[9216]
#define H2LD 72
#define H3LD 136
#define W4LD 136

typedef wmma::fragment<wmma::matrix_a, 16, 16, 8, wmma::precision::tf32, wmma::row_major> FragA;
typedef wmma::fragment<wmma::matrix_b, 16, 16, 8, wmma::precision::tf32, wmma::col_major> FragB;
typedef wmma::fragment<wmma::accumulator, 16, 16, 8, float> FragC;

__global__ __launch_bounds__(256, 1) void l34_kernel(
    const float* __restrict__ w3, const float* __restrict__ w4) {
    extern __shared__ float sm[];
    float* h2s  = sm;                       // 160*72  = 11520
    float* h3s  = h2s + 160 * H2LD;         // 160*136 = 21760
    float* wbuf = h3s + 160 * H3LD;         // 9216 (W3 128x64@72 / W4 64x128@136)

    const int tid = threadIdx.x, warp = tid >> 5;
    const int tile = blockIdx.x;

    // stage h2 tile + W3 (tf32-rounded)
    const float* h2g = g_h2 + (size_t)tile * 160 * C2;
    for (int i = tid; i < 160 * 64; i += 256) {
        int r = i >> 6, k = i & 63;
        h2s[r * H2LD + k] = rna_tf32(h2g[i]);
    }
    for (int i = tid; i < 128 * 64; i += 256) {
        int o = i >> 6, k = i & 63;
        wbuf[o * H2LD + k] = rna_tf32(w3[i]);
    }
    __syncthreads();

    // D1 = h2 @ W3^T : M=160, N=128, K=64
    {
        FragA fa; FragB fb; FragC fc;
        for (int t = warp; t < 80; t += 8) {
            int mt = t >> 3, nt = t & 7;
            wmma::fill_fragment(fc, 0.f);
#pragma unroll
            for (int kt = 0; kt < 8; ++kt) {
                wmma::load_matrix_sync(fa, h2s + mt * 16 * H2LD + kt * 8, H2LD);
                wmma::load_matrix_sync(fb, wbuf + nt * 16 * H2LD + kt * 8, H2LD);
                wmma::mma_sync(fc, fa, fb, fc);
            }
            wmma::store_matrix_sync(h3s + mt * 16 * H3LD + nt * 16, fc, H3LD, wmma::mem_row_major);
        }
    }
    __syncthreads();

    // relu + rna in h3s; x3 maxima -> cat[128..255]
    {
        int oc = tid & 127, pb = (tid >> 7) * 4;
#pragma unroll
        for (int pi = 0; pi < 4; ++pi) {
            int p = pb + pi;
            float mx = 0.f;
#pragma unroll
            for (int r = 0; r < KNN; ++r) {
                float* a = h3s + (p * KNN + r) * H3LD + oc;
                float v = fmaxf(*a, 0.f);
                mx = fmaxf(mx, v);
                *a = rna_tf32(v);
            }
            g_cat[((size_t)tile * 8 + p) * CCAT + 128 + oc] = mx;
        }
    }
    __syncthreads();

    // D2 = h3 @ W4^T : M=160, N=256 (4 chunks of 64), K=128
    for (int co = 0; co < 4; ++co) {
        for (int i = tid; i < 64 * 128; i += 256) {
            int o = i >> 7, k = i & 127;
            wbuf[o * W4LD + k] = rna_tf32(w4[(size_t)(co * 64 + o) * 128 + k]);
        }
        __syncthreads();
        {
            FragA fa; FragB fb; FragC fc;
            for (int t = warp; t < 40; t += 8) {
                int mt = t >> 2, nt = t & 3;
                wmma::fill_fragment(fc, 0.f);
#pragma unroll
                for (int kt = 0; kt < 16; ++kt) {
                    wmma::load_matrix_sync(fa, h3s + mt * 16 * H3LD + kt * 8, H3LD);
                    wmma::load_matrix_sync(fb, wbuf + nt * 16 * W4LD + kt * 8, W4LD);
                    wmma::mma_sync(fc, fa, fb, fc);
                }
                wmma::store_matrix_sync(h2s + mt * 16 * H2LD + nt * 16, fc, H2LD, wmma::mem_row_major);
            }
        }
        __syncthreads();
        {   // x4 maxima for this 64-oc chunk
            int oc = tid & 63, pb = (tid >> 6) * 2;
#pragma unroll
            for (int pi = 0; pi < 2; ++pi) {
                int p = pb + pi;
                float mx = 0.f;
#pragma unroll
                for (int r = 0; r < KNN; ++r)
                    mx = fmaxf(mx, h2s[(p * KNN + r) * H2LD + oc]);
                g_cat[((size_t)tile * 8 + p) * CCAT + 256 + co * 64 + oc] = fmaxf(mx, 0.f);
            }
        }
        __syncthreads();
    }
}

// ===================== Kernel 4: L5 via wmma tf32 =====================
// Block = 32 points. M=32, N=512 (4 oc-chunks of 128), K=512 (4 k-chunks of 128).
#define CATLD 520
#define W5LD  136
#define SCLD  40

__global__ __launch_bounds__(256, 1) void l5_kernel(
    const float* __restrict__ w5, float* __restrict__ out) {
    extern __shared__ float sm[];
    float* cats    = sm;                        // 32*520  = 16640
    float* wbuf    = cats + 32 * CATLD;         // 128*136 = 17408
    float* scratch = wbuf + 128 * W5LD;         // 128*40  = 5120

    const int tid = threadIdx.x, warp = tid >> 5;
    const size_t p0 = (size_t)blockIdx.x * 32;
    const int b = (int)(p0 >> 12), n0 = (int)(p0 & 4095);

    const float* catg = g_cat + p0 * CCAT;
    for (int i = tid; i < 32 * 512; i += 256) {
        int r = i >> 9, k = i & 511;
        cats[r * CATLD + k] = rna_tf32(catg[i]);
    }

    FragA fa; FragB fb;
    for (int co = 0; co < 4; ++co) {
        FragC fc[2];
        wmma::fill_fragment(fc[0], 0.f);
        wmma::fill_fragment(fc[1], 0.f);
        for (int kc = 0; kc < 4; ++kc) {
            __syncthreads();   // covers cats staging (kc=0) and wbuf reuse
            for (int i = tid; i < 128 * 128; i += 256) {
                int o = i >> 7, k = i & 127;
                wbuf[o * W5LD + k] = rna_tf32(w5[(size_t)(co * 128 + o) * CCAT + kc * 128 + k]);
            }
            __syncthreads();
#pragma unroll
            for (int tt = 0; tt < 2; ++tt) {
                int t = warp * 2 + tt;
                int mt = t >> 3, nt = t & 7;
#pragma unroll
                for (int kt = 0; kt < 16; ++kt) {
                    wmma::load_matrix_sync(fa, cats + mt * 16 * CATLD + kc * 128 + kt * 8, CATLD);
                    wmma::load_matrix_sync(fb, wbuf + nt * 16 * W5LD + kt * 8, W5LD);
                    wmma::mma_sync(fc[tt], fa, fb, fc[tt]);
                }
            }
        }
        __syncthreads();   // scratch free (prev co writes done)
#pragma unroll
        for (int tt = 0; tt < 2; ++tt) {
            int t = warp * 2 + tt;
            int mt = t >> 3, nt = t & 7;
            // col-major store: scratch[oc_local][m] with column stride SCLD
            wmma::store_matrix_sync(scratch + nt * 16 * SCLD + mt * 16, fc[tt], SCLD, wmma::mem_col_major);
        }
        __syncthreads();
        for (int i = tid; i < 128 * 32; i += 256) {
            int ol = i >> 5, j = i & 31;
            int o = co * 128 + ol;
            out[((size_t)b * EMB + o) * NPTS + n0 + j] = fmaxf(scratch[ol * SCLD + j], 0.f);
        }
    }
}

// ===================== launch =====================
extern "C" void kernel_launch(void* const* d_in, const int* in_sizes, int n_in,
                              void* d_out, int out_size) {
    const float* x  = (const float*)d_in[0];
    const float* w1 = (const float*)d_in[1];
    const float* w2 = (const float*)d_in[2];
    const float* w3 = (const float*)d_in[3];
    const float* w4 = (const float*)d_in[4];
    const float* w5 = (const float*)d_in[5];
    float* out = (float*)d_out;

    const int knn_smem = NPTS * sizeof(float4);                              // 64 KB
    const int l34_smem = (160 * H2LD + 160 * H3LD + 9216) * sizeof(float);   // ~166 KB
    const int l5_smem  = (32 * CATLD + 128 * W5LD + 128 * SCLD) * sizeof(float); // ~157 KB
    cudaFuncSetAttribute(knn_kernel, cudaFuncAttributeMaxDynamicSharedMemorySize, knn_smem);
    cudaFuncSetAttribute(l34_kernel, cudaFuncAttributeMaxDynamicSharedMemorySize, l34_smem);
    cudaFuncSetAttribute(l5_kernel,  cudaFuncAttributeMaxDynamicSharedMemorySize, l5_smem);

    knn_kernel<<<dim3(NPTS / 256, BATCH), 256, knn_smem>>>(x);
    l12_kernel<<<(BATCH * NPTS) / PTS_PER_BLK, 512>>>(x, w1, w2);
    l34_kernel<<<(BATCH * NPTS) / 8, 256, l34_smem>>>(w3, w4);
    l5_kernel<<<(BATCH * NPTS) / 32, 256, l5_smem>>>(w5, out);
}

// round 5
// speedup vs baseline: 1.4525x; 1.2526x over previous
#include <cuda_runtime.h>
#include <math_constants.h>
#include <mma.h>
#include <cstdint>

using namespace nvcuda;

#define BATCH 8
#define NPTS  4096
#define KNN   20
#define CIN   26
#define C1    64
#define C2    64
#define C3    128
#define C4    256
#define CCAT  512
#define EMB   512

__device__ int   g_idx[BATCH * NPTS * KNN];
__device__ float g_cat[(size_t)BATCH * NPTS * CCAT];     // 64 MB
__device__ float g_h2[(size_t)BATCH * NPTS * KNN * C2];  // 168 MB

__device__ __forceinline__ float rna_tf32(float x) {
    uint32_t o;
    asm("cvt.rna.tf32.f32 %0, %1;" : "=r"(o) : "r"(__float_as_uint(x)));
    return __uint_as_float(o);
}

// ===================== Kernel 1: exact 20-NN =====================
__global__ __launch_bounds__(128) void knn_kernel(const float* __restrict__ x) {
    extern __shared__ float4 xs[];   // 64KB
    const int b = blockIdx.y;
    const float* xb = x + (size_t)b * 3 * NPTS;
    for (int m = threadIdx.x; m < NPTS; m += blockDim.x) {
        float x0 = xb[m], x1 = xb[NPTS + m], x2 = xb[2 * NPTS + m];
        xs[m] = make_float4(x0, x1, x2, fmaf(x0, x0, fmaf(x1, x1, x2 * x2)));
    }
    __syncthreads();
    const int n = blockIdx.x * blockDim.x + threadIdx.x;
    float4 p = xs[n];
    const float a0 = -2.f * p.x, a1 = -2.f * p.y, a2 = -2.f * p.z;
    float bv[KNN]; int bi[KNN];
#pragma unroll
    for (int t = 0; t < KNN; ++t) { bv[t] = CUDART_INF_F; bi[t] = -1; }
#pragma unroll 4
    for (int m = 0; m < NPTS; ++m) {
        float4 q = xs[m];
        float v = fmaf(a0, q.x, fmaf(a1, q.y, fmaf(a2, q.z, q.w)));
        if (v < bv[KNN - 1]) {
            bool ins = true;
#pragma unroll
            for (int t = KNN - 1; t >= 1; --t) {
                bool sh = v < bv[t - 1];
                if (sh)       { bv[t] = bv[t - 1]; bi[t] = bi[t - 1]; }
                else if (ins) { bv[t] = v;         bi[t] = m; }
                ins = sh;
            }
            if (ins) { bv[0] = v; bi[0] = m; }
        }
    }
    int* outp = g_idx + ((size_t)b * NPTS + n) * KNN;
#pragma unroll
    for (int t = 0; t < KNN; ++t) outp[t] = bi[t];
}

// ===================== Kernel 2: feature + L1 + L2 (scalar) =====================
#define PTS_PER_BLK 8
__global__ __launch_bounds__(512) void l12_kernel(
    const float* __restrict__ x, const float* __restrict__ w1, const float* __restrict__ w2) {
    __shared__ float W1t[CIN * C1], W2t[C2 * C2];
    __shared__ float h1[KNN * C1], h2[KNN * C2];
    __shared__ float s_nbr[KNN * 4], s_dist[KNN], s_base[C1], s_xn[4];
    const int tid = threadIdx.x;
    for (int i = tid; i < C1 * CIN; i += 512) { int o = i / CIN, c = i % CIN; W1t[c * C1 + o] = w1[i]; }
    for (int i = tid; i < C2 * C2;  i += 512) { int o = i >> 6,  c = i & 63;  W2t[c * C2 + o] = w2[i]; }
    __syncthreads();

    for (int pp = 0; pp < PTS_PER_BLK; ++pp) {
        const int pt = blockIdx.x * PTS_PER_BLK + pp;
        const int b = pt >> 12, n = pt & (NPTS - 1);
        const float* xb = x + (size_t)b * 3 * NPTS;
        if (tid < 3) s_xn[tid] = xb[tid * NPTS + n];
        if (tid < KNN) {
            int nb = g_idx[((size_t)b * NPTS + n) * KNN + tid];
            float c0 = xb[n], c1 = xb[NPTS + n], c2 = xb[2 * NPTS + n];
            float n0 = xb[nb], n1 = xb[NPTS + nb], n2 = xb[2 * NPTS + nb];
            s_nbr[tid * 4 + 0] = n0; s_nbr[tid * 4 + 1] = n1; s_nbr[tid * 4 + 2] = n2;
            float d0 = n0 - c0, d1 = n1 - c1, d2 = n2 - c2;
            s_dist[tid] = sqrtf(fmaf(d0, d0, fmaf(d1, d1, d2 * d2)) + 1e-12f);
        }
        __syncthreads();
        if (tid < C1) {
            float acc = 0.f;
#pragma unroll
            for (int d = 0; d < 3; ++d) acc = fmaf(W1t[d * C1 + tid], s_xn[d], acc);
#pragma unroll
            for (int j = 0; j < KNN; ++j) acc = fmaf(W1t[(6 + j) * C1 + tid], s_dist[j], acc);
            s_base[tid] = acc;
        }
        __syncthreads();
        {   // layer 1
            int o = tid & 63, g = tid >> 6;
            float wa = W1t[3 * C1 + o], wb = W1t[4 * C1 + o], wc = W1t[5 * C1 + o];
            float base = s_base[o];
#pragma unroll
            for (int j = 0; j < 3; ++j) {
                int k = g + 8 * j;
                if (j < 2 || g < 4) {
                    float v = fmaf(wa, s_nbr[k * 4], fmaf(wb, s_nbr[k * 4 + 1], fmaf(wc, s_nbr[k * 4 + 2], base)));
                    h1[k * C1 + o] = fmaxf(v, 0.f);
                }
            }
        }
        __syncthreads();
        {   // layer 2 (+ spill rows)
            int o = tid & 63, g = tid >> 6;
            float a0 = 0.f, a1 = 0.f, a2 = 0.f;
#pragma unroll
            for (int c = 0; c < C2; c += 4) {
                float w0 = W2t[c * C2 + o], wA = W2t[(c + 1) * C2 + o];
                float wB = W2t[(c + 2) * C2 + o], wC = W2t[(c + 3) * C2 + o];
                float4 hA = *(const float4*)(h1 + g * C1 + c);
                float4 hB = *(const float4*)(h1 + (g + 8) * C1 + c);
                a0 = fmaf(w0, hA.x, fmaf(wA, hA.y, fmaf(wB, hA.z, fmaf(wC, hA.w, a0))));
                a1 = fmaf(w0, hB.x, fmaf(wA, hB.y, fmaf(wB, hB.z, fmaf(wC, hB.w, a1))));
                if (g < 4) {
                    float4 hC = *(const float4*)(h1 + (g + 16) * C1 + c);
                    a2 = fmaf(w0, hC.x, fmaf(wA, hC.y, fmaf(wB, hC.z, fmaf(wC, hC.w, a2))));
                }
            }
            float* hr = g_h2 + (size_t)pt * KNN * C2;
            float v0 = fmaxf(a0, 0.f); h2[g * C2 + o] = v0;        hr[g * C2 + o] = v0;
            float v1 = fmaxf(a1, 0.f); h2[(g + 8) * C2 + o] = v1;  hr[(g + 8) * C2 + o] = v1;
            if (g < 4) { float v2 = fmaxf(a2, 0.f); h2[(g + 16) * C2 + o] = v2; hr[(g + 16) * C2 + o] = v2; }
        }
        __syncthreads();
        if (tid < 64) {
            float m = 0.f;
#pragma unroll
            for (int k = 0; k < KNN; ++k) m = fmaxf(m, h1[k * C1 + tid]);
            g_cat[(size_t)pt * CCAT + tid] = m;
        } else if (tid < 128) {
            int o = tid - 64; float m = 0.f;
#pragma unroll
            for (int k = 0; k < KNN; ++k) m = fmaxf(m, h2[k * C2 + o]);
            g_cat[(size_t)pt * CCAT + 64 + o] = m;
        }
        __syncthreads();
    }
}

// ===================== Kernel 3: L3+L4 via wmma tf32 =====================
// Block = 4 points = 80 rows. 256 threads. ~103KB smem -> 2 blocks/SM.
#define L34PTS 4
#define L34ROWS (L34PTS * KNN)   // 80
#define H2LD 72
#define H3LD 136
#define W4LD 136

typedef wmma::fragment<wmma::matrix_a, 16, 16, 8, wmma::precision::tf32, wmma::row_major> FragA;
typedef wmma::fragment<wmma::matrix_b, 16, 16, 8, wmma::precision::tf32, wmma::col_major> FragB;
typedef wmma::fragment<wmma::accumulator, 16, 16, 8, float> FragC;

__global__ __launch_bounds__(256, 2) void l34_kernel(
    const float* __restrict__ w3, const float* __restrict__ w4) {
    extern __shared__ float sm[];
    float* h2s  = sm;                           // 80*72  = 5760
    float* h3s  = h2s + L34ROWS * H2LD;         // 80*136 = 10880
    float* wbuf = h3s + L34ROWS * H3LD;         // 9216

    const int tid = threadIdx.x, warp = tid >> 5;
    const int tile = blockIdx.x;

    const float* h2g = g_h2 + (size_t)tile * L34ROWS * C2;
    for (int i = tid; i < L34ROWS * 64; i += 256) {
        int r = i >> 6, k = i & 63;
        h2s[r * H2LD + k] = rna_tf32(h2g[i]);
    }
    for (int i = tid; i < 128 * 64; i += 256) {
        int o = i >> 6, k = i & 63;
        wbuf[o * H2LD + k] = rna_tf32(w3[i]);
    }
    __syncthreads();

    // D1 = h2 @ W3^T : M=80, N=128, K=64  (40 tiles)
    {
        FragA fa; FragB fb; FragC fc;
        for (int t = warp; t < 40; t += 8) {
            int mt = t >> 3, nt = t & 7;
            wmma::fill_fragment(fc, 0.f);
#pragma unroll
            for (int kt = 0; kt < 8; ++kt) {
                wmma::load_matrix_sync(fa, h2s + mt * 16 * H2LD + kt * 8, H2LD);
                wmma::load_matrix_sync(fb, wbuf + nt * 16 * H2LD + kt * 8, H2LD);
                wmma::mma_sync(fc, fa, fb, fc);
            }
            wmma::store_matrix_sync(h3s + mt * 16 * H3LD + nt * 16, fc, H3LD, wmma::mem_row_major);
        }
    }
    __syncthreads();

    // relu + rna in h3s; x3 maxima -> cat[128..255]
    {
        int oc = tid & 127, pb = (tid >> 7) * 2;   // 2 points per thread
#pragma unroll
        for (int pi = 0; pi < 2; ++pi) {
            int p = pb + pi;
            float mx = 0.f;
#pragma unroll
            for (int r = 0; r < KNN; ++r) {
                float* a = h3s + (p * KNN + r) * H3LD + oc;
                float v = fmaxf(*a, 0.f);
                mx = fmaxf(mx, v);
                *a = rna_tf32(v);
            }
            g_cat[((size_t)tile * L34PTS + p) * CCAT + 128 + oc] = mx;
        }
    }
    __syncthreads();

    // D2 = h3 @ W4^T : M=80, N=256 (4 chunks of 64), K=128
    for (int co = 0; co < 4; ++co) {
        for (int i = tid; i < 64 * 128; i += 256) {
            int o = i >> 7, k = i & 127;
            wbuf[o * W4LD + k] = rna_tf32(w4[(size_t)(co * 64 + o) * 128 + k]);
        }
        __syncthreads();
        {
            FragA fa; FragB fb; FragC fc;
            for (int t = warp; t < 20; t += 8) {
                int mt = t >> 2, nt = t & 3;
                wmma::fill_fragment(fc, 0.f);
#pragma unroll
                for (int kt = 0; kt < 16; ++kt) {
                    wmma::load_matrix_sync(fa, h3s + mt * 16 * H3LD + kt * 8, H3LD);
                    wmma::load_matrix_sync(fb, wbuf + nt * 16 * W4LD + kt * 8, W4LD);
                    wmma::mma_sync(fc, fa, fb, fc);
                }
                wmma::store_matrix_sync(h2s + mt * 16 * H2LD + nt * 16, fc, H2LD, wmma::mem_row_major);
            }
        }
        __syncthreads();
        {   // x4 maxima for this 64-oc chunk (1 point per thread)
            int oc = tid & 63, p = tid >> 6;
            float mx = 0.f;
#pragma unroll
            for (int r = 0; r < KNN; ++r)
                mx = fmaxf(mx, h2s[(p * KNN + r) * H2LD + oc]);
            g_cat[((size_t)tile * L34PTS + p) * CCAT + 256 + co * 64 + oc] = fmaxf(mx, 0.f);
        }
        __syncthreads();
    }
}

// ===================== Kernel 4: L5 classic tiled GEMM (wmma tf32) =====================
// out[b][o][n] = relu(w5[o,:] . cat[b*4096+n, :])
// Block tile: 128(o) x 128(n), K=512 in chunks of 32, double-buffered.
#define KC   32
#define ALD  36           // padded ld for A/B tiles
#define TILEFL (128 * ALD)   // floats per tile buffer (4608)

__global__ __launch_bounds__(256, 2) void l5_kernel(
    const float* __restrict__ w5, float* __restrict__ out) {
    extern __shared__ float sm[];
    // buffers: A0 B0 A1 B1, each 4608 floats -> 18432 floats = 72KB
    float* bufA[2] = { sm,             sm + 2 * TILEFL };
    float* bufB[2] = { sm + TILEFL,    sm + 3 * TILEFL };

    const int tid = threadIdx.x, warp = tid >> 5;
    const int n0 = blockIdx.x * 128;          // point offset within batch
    const int o0 = blockIdx.y * 128;
    const int b  = blockIdx.z;
    const float* catg = g_cat + ((size_t)b * NPTS + n0) * CCAT;
    const float* wg   = w5 + (size_t)o0 * CCAT;

    // warp grid 2x4: warp tile 64(o) x 32(n)
    const int wr = warp >> 2, wc = warp & 3;

    FragC fc[4][2];
#pragma unroll
    for (int i = 0; i < 4; ++i) { wmma::fill_fragment(fc[i][0], 0.f); wmma::fill_fragment(fc[i][1], 0.f); }

    // stage chunk kc into buffer bi
    auto stage = [&](int kc, int bi) {
        const int row = tid >> 1, v = tid & 1;       // 2 float4-pairs... 128 rows x 8 float4
        // each thread: 4 float4 of A, 4 float4 of B (128*8 float4 per tile / 256 thr = 4)
#pragma unroll
        for (int it = 0; it < 4; ++it) {
            int r = (tid >> 3) + it * 32;            // 0..127
            int q = tid & 7;                          // float4 idx 0..7
            float4 a = *(const float4*)(wg   + (size_t)r * CCAT + kc * KC + q * 4);
            float4 c = *(const float4*)(catg + (size_t)r * CCAT + kc * KC + q * 4);
            a.x = rna_tf32(a.x); a.y = rna_tf32(a.y); a.z = rna_tf32(a.z); a.w = rna_tf32(a.w);
            c.x = rna_tf32(c.x); c.y = rna_tf32(c.y); c.z = rna_tf32(c.z); c.w = rna_tf32(c.w);
            float* pa = bufA[bi] + r * ALD + q * 4;
            float* pb = bufB[bi] + r * ALD + q * 4;
            pa[0] = a.x; pa[1] = a.y; pa[2] = a.z; pa[3] = a.w;
            pb[0] = c.x; pb[1] = c.y; pb[2] = c.z; pb[3] = c.w;
        }
        (void)row; (void)v;
    };

    stage(0, 0);
    __syncthreads();

    FragA fa; FragB fb;
    for (int kc = 0; kc < 16; ++kc) {
        const int cur = kc & 1;
        if (kc + 1 < 16) stage(kc + 1, cur ^ 1);
        const float* A = bufA[cur];
        const float* B = bufB[cur];
#pragma unroll
        for (int kt = 0; kt < 4; ++kt) {
#pragma unroll
            for (int j = 0; j < 2; ++j) {
                wmma::load_matrix_sync(fb, B + (wc * 32 + j * 16) * ALD + kt * 8, ALD);
#pragma unroll
                for (int i = 0; i < 4; ++i) {
                    wmma::load_matrix_sync(fa, A + (wr * 64 + i * 16) * ALD + kt * 8, ALD);
                    wmma::mma_sync(fc[i][j], fa, fb, fc[i][j]);
                }
            }
        }
        __syncthreads();
    }

    // epilogue: fc -> scratch[o][n] (ld 132), then coalesced relu-store
    float* scratch = sm;   // 128*132 = 16896 floats = 67.6KB <= 72KB
#pragma unroll
    for (int i = 0; i < 4; ++i)
#pragma unroll
        for (int j = 0; j < 2; ++j)
            wmma::store_matrix_sync(scratch + (wr * 64 + i * 16) * 132 + wc * 32 + j * 16,
                                    fc[i][j], 132, wmma::mem_row_major);
    __syncthreads();

    for (int i = tid; i < 128 * 128; i += 256) {
        int o = i >> 7, n = i & 127;
        out[((size_t)b * EMB + o0 + o) * NPTS + n0 + n] = fmaxf(scratch[o * 132 + n], 0.f);
    }
}

// ===================== launch =====================
extern "C" void kernel_launch(void* const* d_in, const int* in_sizes, int n_in,
                              void* d_out, int out_size) {
    const float* x  = (const float*)d_in[0];
    const float* w1 = (const float*)d_in[1];
    const float* w2 = (const float*)d_in[2];
    const float* w3 = (const float*)d_in[3];
    const float* w4 = (const float*)d_in[4];
    const float* w5 = (const float*)d_in[5];
    float* out = (float*)d_out;

    const int knn_smem = NPTS * sizeof(float4);                                  // 64 KB
    const int l34_smem = (L34ROWS * H2LD + L34ROWS * H3LD + 9216) * sizeof(float); // ~103 KB
    const int l5_smem  = (4 * TILEFL) * sizeof(float);                           // 72 KB (>=128*132*4=67.6KB)
    cudaFuncSetAttribute(knn_kernel, cudaFuncAttributeMaxDynamicSharedMemorySize, knn_smem);
    cudaFuncSetAttribute(l34_kernel, cudaFuncAttributeMaxDynamicSharedMemorySize, l34_smem);
    cudaFuncSetAttribute(l5_kernel,  cudaFuncAttributeMaxDynamicSharedMemorySize, l5_smem);

    knn_kernel<<<dim3(NPTS / 128, BATCH), 128, knn_smem>>>(x);
    l12_kernel<<<(BATCH * NPTS) / PTS_PER_BLK, 512>>>(x, w1, w2);
    l34_kernel<<<(BATCH * NPTS) / L34PTS, 256, l34_smem>>>(w3, w4);
    l5_kernel<<<dim3(NPTS / 128, EMB / 128, BATCH), 256, l5_smem>>>(w5, out);
}

// round 6
// speedup vs baseline: 1.6877x; 1.1619x over previous
#include <cuda_runtime.h>
#include <math_constants.h>
#include <mma.h>
#include <cstdint>

using namespace nvcuda;

#define BATCH 8
#define NPTS  4096
#define KNN   20
#define CIN   26
#define C1    64
#define C2    64
#define C3    128
#define C4    256
#define CCAT  512
#define EMB   512

__device__ int   g_idx[BATCH * NPTS * KNN];
__device__ float g_cat[(size_t)BATCH * NPTS * CCAT];     // 64 MB

__device__ __forceinline__ float rna_tf32(float x) {
    uint32_t o;
    asm("cvt.rna.tf32.f32 %0, %1;" : "=r"(o) : "r"(__float_as_uint(x)));
    return __uint_as_float(o);
}

// ===================== Kernel 1: exact 20-NN =====================
__global__ __launch_bounds__(128) void knn_kernel(const float* __restrict__ x) {
    extern __shared__ float4 xs[];   // 64KB
    const int b = blockIdx.y;
    const float* xb = x + (size_t)b * 3 * NPTS;
    for (int m = threadIdx.x; m < NPTS; m += blockDim.x) {
        float x0 = xb[m], x1 = xb[NPTS + m], x2 = xb[2 * NPTS + m];
        xs[m] = make_float4(x0, x1, x2, fmaf(x0, x0, fmaf(x1, x1, x2 * x2)));
    }
    __syncthreads();
    const int n = blockIdx.x * blockDim.x + threadIdx.x;
    float4 p = xs[n];
    const float a0 = -2.f * p.x, a1 = -2.f * p.y, a2 = -2.f * p.z;
    float bv[KNN]; int bi[KNN];
#pragma unroll
    for (int t = 0; t < KNN; ++t) { bv[t] = CUDART_INF_F; bi[t] = -1; }
#pragma unroll 4
    for (int m = 0; m < NPTS; ++m) {
        float4 q = xs[m];
        float v = fmaf(a0, q.x, fmaf(a1, q.y, fmaf(a2, q.z, q.w)));
        if (v < bv[KNN - 1]) {
            bool ins = true;
#pragma unroll
            for (int t = KNN - 1; t >= 1; --t) {
                bool sh = v < bv[t - 1];
                if (sh)       { bv[t] = bv[t - 1]; bi[t] = bi[t - 1]; }
                else if (ins) { bv[t] = v;         bi[t] = m; }
                ins = sh;
            }
            if (ins) { bv[0] = v; bi[0] = m; }
        }
    }
    int* outp = g_idx + ((size_t)b * NPTS + n) * KNN;
#pragma unroll
    for (int t = 0; t < KNN; ++t) outp[t] = bi[t];
}

// ===================== Kernel 2: fused L1(scalar) + L2/L3/L4 (wmma tf32) =====================
// Block = 4 points = 80 rows, 256 threads, ~103KB smem -> 2 blocks/SM.
#define L34PTS 4
#define L34ROWS (L34PTS * KNN)   // 80
#define H2LD 72
#define H3LD 136
#define W4LD 136

typedef wmma::fragment<wmma::matrix_a, 16, 16, 8, wmma::precision::tf32, wmma::row_major> FragA;
typedef wmma::fragment<wmma::matrix_b, 16, 16, 8, wmma::precision::tf32, wmma::col_major> FragB;
typedef wmma::fragment<wmma::accumulator, 16, 16, 8, float> FragC;

__global__ __launch_bounds__(256, 2) void l1234_kernel(
    const float* __restrict__ x,
    const float* __restrict__ w1, const float* __restrict__ w2,
    const float* __restrict__ w3, const float* __restrict__ w4) {
    extern __shared__ float sm[];
    float* h2s  = sm;                           // 80*72  = 5760  (W1t staging first)
    float* h3s  = h2s + L34ROWS * H2LD;         // 80*136 = 10880 (h1 first, then h3)
    float* wbuf = h3s + L34ROWS * H3LD;         // 9216 (W2 / W3 / W4-chunks)
    __shared__ float s_nbr[L34PTS][KNN][3];
    __shared__ float s_dist[L34PTS][KNN];
    __shared__ float s_xn[L34PTS][3];

    const int tid = threadIdx.x, warp = tid >> 5;
    const size_t pt0 = (size_t)blockIdx.x * L34PTS;

    // stage W1 -> h2s area ([c][o]); W2 -> wbuf ([o][c], ld H2LD, tf32)
    for (int i = tid; i < CIN * C1; i += 256) { int o = i / CIN, c = i % CIN; h2s[c * C1 + o] = w1[i]; }
    for (int i = tid; i < C2 * C2;  i += 256) { int o = i >> 6,  c = i & 63;  wbuf[o * H2LD + c] = rna_tf32(w2[i]); }

    // gather neighbors + dist
    if (tid < L34PTS * KNN) {
        int p = tid / KNN, k = tid % KNN;
        size_t pt = pt0 + p;
        int b = (int)(pt >> 12), n = (int)(pt & (NPTS - 1));
        const float* xb = x + (size_t)b * 3 * NPTS;
        int nb = g_idx[pt * KNN + k];
        float c0 = xb[n], c1 = xb[NPTS + n], c2 = xb[2 * NPTS + n];
        float n0 = xb[nb], n1 = xb[NPTS + nb], n2 = xb[2 * NPTS + nb];
        s_nbr[p][k][0] = n0; s_nbr[p][k][1] = n1; s_nbr[p][k][2] = n2;
        float d0 = n0 - c0, d1 = n1 - c1, d2 = n2 - c2;
        s_dist[p][k] = sqrtf(fmaf(d0, d0, fmaf(d1, d1, d2 * d2)) + 1e-12f);
        if (k < 3) s_xn[p][k] = xb[k * NPTS + n];
    }
    __syncthreads();

    // ---- L1 scalar: h1 rows -> h3s (tf32), x1 -> cat[0:64] ----
    {
        int o = tid & 63, p = tid >> 6;
        float base = 0.f;
#pragma unroll
        for (int d = 0; d < 3; ++d) base = fmaf(h2s[d * C1 + o], s_xn[p][d], base);
#pragma unroll
        for (int j = 0; j < KNN; ++j) base = fmaf(h2s[(6 + j) * C1 + o], s_dist[p][j], base);
        float wa = h2s[3 * C1 + o], wb = h2s[4 * C1 + o], wc = h2s[5 * C1 + o];
        float mx = 0.f;
#pragma unroll
        for (int k = 0; k < KNN; ++k) {
            float v = fmaf(wa, s_nbr[p][k][0], fmaf(wb, s_nbr[p][k][1], fmaf(wc, s_nbr[p][k][2], base)));
            v = fmaxf(v, 0.f);
            mx = fmaxf(mx, v);
            h3s[(p * KNN + k) * H3LD + o] = rna_tf32(v);
        }
        g_cat[(pt0 + p) * CCAT + o] = mx;
    }
    __syncthreads();

    // ---- L2 GEMM: h2 = h1 @ W2^T : M=80, N=64, K=64 (20 tiles) -> h2s ----
    {
        FragA fa; FragB fb; FragC fc;
        for (int t = warp; t < 20; t += 8) {
            int mt = t >> 2, nt = t & 3;
            wmma::fill_fragment(fc, 0.f);
#pragma unroll
            for (int kt = 0; kt < 8; ++kt) {
                wmma::load_matrix_sync(fa, h3s + mt * 16 * H3LD + kt * 8, H3LD);
                wmma::load_matrix_sync(fb, wbuf + nt * 16 * H2LD + kt * 8, H2LD);
                wmma::mma_sync(fc, fa, fb, fc);
            }
            wmma::store_matrix_sync(h2s + mt * 16 * H2LD + nt * 16, fc, H2LD, wmma::mem_row_major);
        }
    }
    __syncthreads();

    // relu + rna + x2 -> cat[64:128]
    {
        int o = tid & 63, p = tid >> 6;
        float mx = 0.f;
#pragma unroll
        for (int k = 0; k < KNN; ++k) {
            float* a = h2s + (p * KNN + k) * H2LD + o;
            float v = fmaxf(*a, 0.f);
            mx = fmaxf(mx, v);
            *a = rna_tf32(v);
        }
        g_cat[(pt0 + p) * CCAT + 64 + o] = mx;
    }
    __syncthreads();

    // stage W3 -> wbuf ([o][c], ld H2LD)
    for (int i = tid; i < C3 * C2; i += 256) { int o = i >> 6, c = i & 63; wbuf[o * H2LD + c] = rna_tf32(w3[i]); }
    __syncthreads();

    // ---- L3 GEMM: h3 = h2 @ W3^T : M=80, N=128, K=64 (40 tiles) -> h3s ----
    {
        FragA fa; FragB fb; FragC fc;
        for (int t = warp; t < 40; t += 8) {
            int mt = t >> 3, nt = t & 7;
            wmma::fill_fragment(fc, 0.f);
#pragma unroll
            for (int kt = 0; kt < 8; ++kt) {
                wmma::load_matrix_sync(fa, h2s + mt * 16 * H2LD + kt * 8, H2LD);
                wmma::load_matrix_sync(fb, wbuf + nt * 16 * H2LD + kt * 8, H2LD);
                wmma::mma_sync(fc, fa, fb, fc);
            }
            wmma::store_matrix_sync(h3s + mt * 16 * H3LD + nt * 16, fc, H3LD, wmma::mem_row_major);
        }
    }
    __syncthreads();

    // relu + rna + x3 -> cat[128:256] (2 points per thread)
    {
        int oc = tid & 127, pb = (tid >> 7) * 2;
#pragma unroll
        for (int pi = 0; pi < 2; ++pi) {
            int p = pb + pi;
            float mx = 0.f;
#pragma unroll
            for (int r = 0; r < KNN; ++r) {
                float* a = h3s + (p * KNN + r) * H3LD + oc;
                float v = fmaxf(*a, 0.f);
                mx = fmaxf(mx, v);
                *a = rna_tf32(v);
            }
            g_cat[(pt0 + p) * CCAT + 128 + oc] = mx;
        }
    }
    __syncthreads();

    // ---- L4 GEMM: D2 = h3 @ W4^T : M=80, N=256 (4 chunks of 64), K=128 ----
    for (int co = 0; co < 4; ++co) {
        for (int i = tid; i < 64 * 128; i += 256) {
            int o = i >> 7, k = i & 127;
            wbuf[o * W4LD + k] = rna_tf32(w4[(size_t)(co * 64 + o) * 128 + k]);
        }
        __syncthreads();
        {
            FragA fa; FragB fb; FragC fc;
            for (int t = warp; t < 20; t += 8) {
                int mt = t >> 2, nt = t & 3;
                wmma::fill_fragment(fc, 0.f);
#pragma unroll
                for (int kt = 0; kt < 16; ++kt) {
                    wmma::load_matrix_sync(fa, h3s + mt * 16 * H3LD + kt * 8, H3LD);
                    wmma::load_matrix_sync(fb, wbuf + nt * 16 * W4LD + kt * 8, W4LD);
                    wmma::mma_sync(fc, fa, fb, fc);
                }
                wmma::store_matrix_sync(h2s + mt * 16 * H2LD + nt * 16, fc, H2LD, wmma::mem_row_major);
            }
        }
        __syncthreads();
        {   // x4 maxima for this 64-oc chunk
            int oc = tid & 63, p = tid >> 6;
            float mx = 0.f;
#pragma unroll
            for (int r = 0; r < KNN; ++r)
                mx = fmaxf(mx, h2s[(p * KNN + r) * H2LD + oc]);
            g_cat[(pt0 + p) * CCAT + 256 + co * 64 + oc] = fmaxf(mx, 0.f);
        }
        __syncthreads();
    }
}

// ===================== Kernel 3: L5 classic tiled GEMM (wmma tf32) =====================
#define KC   32
#define ALD  36
#define TILEFL (128 * ALD)

__global__ __launch_bounds__(256, 2) void l5_kernel(
    const float* __restrict__ w5, float* __restrict__ out) {
    extern __shared__ float sm[];
    float* bufA[2] = { sm,          sm + 2 * TILEFL };
    float* bufB[2] = { sm + TILEFL, sm + 3 * TILEFL };

    const int tid = threadIdx.x, warp = tid >> 5;
    const int n0 = blockIdx.x * 128;
    const int o0 = blockIdx.y * 128;
    const int b  = blockIdx.z;
    const float* catg = g_cat + ((size_t)b * NPTS + n0) * CCAT;
    const float* wg   = w5 + (size_t)o0 * CCAT;

    const int wr = warp >> 2, wc = warp & 3;

    FragC fc[4][2];
#pragma unroll
    for (int i = 0; i < 4; ++i) { wmma::fill_fragment(fc[i][0], 0.f); wmma::fill_fragment(fc[i][1], 0.f); }

    auto stage = [&](int kc, int bi) {
#pragma unroll
        for (int it = 0; it < 4; ++it) {
            int r = (tid >> 3) + it * 32;
            int q = tid & 7;
            float4 a = *(const float4*)(wg   + (size_t)r * CCAT + kc * KC + q * 4);
            float4 c = *(const float4*)(catg + (size_t)r * CCAT + kc * KC + q * 4);
            a.x = rna_tf32(a.x); a.y = rna_tf32(a.y); a.z = rna_tf32(a.z); a.w = rna_tf32(a.w);
            c.x = rna_tf32(c.x); c.y = rna_tf32(c.y); c.z = rna_tf32(c.z); c.w = rna_tf32(c.w);
            float* pa = bufA[bi] + r * ALD + q * 4;
            float* pb = bufB[bi] + r * ALD + q * 4;
            pa[0] = a.x; pa[1] = a.y; pa[2] = a.z; pa[3] = a.w;
            pb[0] = c.x; pb[1] = c.y; pb[2] = c.z; pb[3] = c.w;
        }
    };

    stage(0, 0);
    __syncthreads();

    FragA fa; FragB fb;
    for (int kc = 0; kc < 16; ++kc) {
        const int cur = kc & 1;
        if (kc + 1 < 16) stage(kc + 1, cur ^ 1);
        const float* A = bufA[cur];
        const float* B = bufB[cur];
#pragma unroll
        for (int kt = 0; kt < 4; ++kt) {
#pragma unroll
            for (int j = 0; j < 2; ++j) {
                wmma::load_matrix_sync(fb, B + (wc * 32 + j * 16) * ALD + kt * 8, ALD);
#pragma unroll
                for (int i = 0; i < 4; ++i) {
                    wmma::load_matrix_sync(fa, A + (wr * 64 + i * 16) * ALD + kt * 8, ALD);
                    wmma::mma_sync(fc[i][j], fa, fb, fc[i][j]);
                }
            }
        }
        __syncthreads();
    }

    float* scratch = sm;   // 128*132 = 67.6KB <= 72KB
#pragma unroll
    for (int i = 0; i < 4; ++i)
#pragma unroll
        for (int j = 0; j < 2; ++j)
            wmma::store_matrix_sync(scratch + (wr * 64 + i * 16) * 132 + wc * 32 + j * 16,
                                    fc[i][j], 132, wmma::mem_row_major);
    __syncthreads();

    for (int i = tid; i < 128 * 128; i += 256) {
        int o = i >> 7, n = i & 127;
        out[((size_t)b * EMB + o0 + o) * NPTS + n0 + n] = fmaxf(scratch[o * 132 + n], 0.f);
    }
}

// ===================== launch =====================
extern "C" void kernel_launch(void* const* d_in, const int* in_sizes, int n_in,
                              void* d_out, int out_size) {
    const float* x  = (const float*)d_in[0];
    const float* w1 = (const float*)d_in[1];
    const float* w2 = (const float*)d_in[2];
    const float* w3 = (const float*)d_in[3];
    const float* w4 = (const float*)d_in[4];
    const float* w5 = (const float*)d_in[5];
    float* out = (float*)d_out;

    const int knn_smem   = NPTS * sizeof(float4);                                   // 64 KB
    const int l1234_smem = (L34ROWS * H2LD + L34ROWS * H3LD + 9216) * sizeof(float); // ~103 KB
    const int l5_smem    = (4 * TILEFL) * sizeof(float);                            // 72 KB
    cudaFuncSetAttribute(knn_kernel,   cudaFuncAttributeMaxDynamicSharedMemorySize, knn_smem);
    cudaFuncSetAttribute(l1234_kernel, cudaFuncAttributeMaxDynamicSharedMemorySize, l1234_smem);
    cudaFuncSetAttribute(l5_kernel,    cudaFuncAttributeMaxDynamicSharedMemorySize, l5_smem);

    knn_kernel<<<dim3(NPTS / 128, BATCH), 128, knn_smem>>>(x);
    l1234_kernel<<<(BATCH * NPTS) / L34PTS, 256, l1234_smem>>>(x, w1, w2, w3, w4);
    l5_kernel<<<dim3(NPTS / 128, EMB / 128, BATCH), 256, l5_smem>>>(w5, out);
}

// round 7
// speedup vs baseline: 2.8575x; 1.6931x over previous
#include <cuda_runtime.h>
#include <math_constants.h>
#include <mma.h>
#include <cuda_fp16.h>
#include <cstdint>

using namespace nvcuda;

#define BATCH 8
#define NPTS  4096
#define KNN   20
#define CIN   26
#define C1    64
#define C2    64
#define C3    128
#define C4    256
#define CCAT  512
#define EMB   512

__device__ int   g_idx[BATCH * NPTS * KNN];
__device__ float g_cat[(size_t)BATCH * NPTS * CCAT];     // 64 MB

// ===================== Kernel 1: exact 20-NN, 4 threads/point =====================
__global__ __launch_bounds__(256) void knn_kernel(const float* __restrict__ x) {
    extern __shared__ float4 xs[];          // 64KB
    __shared__ float mv[64][80];
    __shared__ int   mi[64][80];
    const int b = blockIdx.y;
    const float* xb = x + (size_t)b * 3 * NPTS;
    for (int m = threadIdx.x; m < NPTS; m += 256) {
        float x0 = xb[m], x1 = xb[NPTS + m], x2 = xb[2 * NPTS + m];
        xs[m] = make_float4(x0, x1, x2, fmaf(x0, x0, fmaf(x1, x1, x2 * x2)));
    }
    __syncthreads();
    const int lp = threadIdx.x >> 2;        // local point 0..63
    const int c  = threadIdx.x & 3;         // chunk 0..3
    const int n  = blockIdx.x * 64 + lp;
    float4 p = xs[n];
    const float a0 = -2.f * p.x, a1 = -2.f * p.y, a2 = -2.f * p.z;
    float bv[KNN]; int bi[KNN];
#pragma unroll
    for (int t = 0; t < KNN; ++t) { bv[t] = CUDART_INF_F; bi[t] = 0x7FFFFFFF; }
    const int m0 = c * 1024;
#pragma unroll 4
    for (int mm = 0; mm < 1024; ++mm) {
        int m = m0 + mm;
        float4 q = xs[m];
        float v = fmaf(a0, q.x, fmaf(a1, q.y, fmaf(a2, q.z, q.w)));
        if (v < bv[KNN - 1]) {
            bool ins = true;
#pragma unroll
            for (int t = KNN - 1; t >= 1; --t) {
                bool sh = v < bv[t - 1];
                if (sh)       { bv[t] = bv[t - 1]; bi[t] = bi[t - 1]; }
                else if (ins) { bv[t] = v;         bi[t] = m; }
                ins = sh;
            }
            if (ins) { bv[0] = v; bi[0] = m; }
        }
    }
#pragma unroll
    for (int t = 0; t < KNN; ++t) { mv[lp][c * KNN + t] = bv[t]; mi[lp][c * KNN + t] = bi[t]; }
    __syncthreads();
    if (c == 0) {
        for (int e = KNN; e < 80; ++e) {
            float v = mv[lp][e]; int i = mi[lp][e];
            if (v < bv[KNN - 1] || (v == bv[KNN - 1] && i < bi[KNN - 1])) {
                bool ins = true;
#pragma unroll
                for (int t = KNN - 1; t >= 1; --t) {
                    bool sh = (v < bv[t - 1]) || (v == bv[t - 1] && i < bi[t - 1]);
                    if (sh)       { bv[t] = bv[t - 1]; bi[t] = bi[t - 1]; }
                    else if (ins) { bv[t] = v;         bi[t] = i; }
                    ins = sh;
                }
                if (ins) { bv[0] = v; bi[0] = i; }
            }
        }
        int* outp = g_idx + ((size_t)b * NPTS + n) * KNN;
#pragma unroll
        for (int t = 0; t < KNN; ++t) outp[t] = bi[t];
    }
}

// ===================== Kernel 2: fused L1(scalar) + L2/L3/L4 (wmma fp16) =====================
// Block = 8 points = 160 rows, 256 threads, ~85KB dyn smem -> 2 blocks/SM.
#define LPTS 8
#define LROWS (LPTS * KNN)   // 160
#define HBLD 136             // halves
#define H2LD2 72             // halves

typedef wmma::fragment<wmma::matrix_a, 16, 16, 16, half, wmma::row_major> HA;
typedef wmma::fragment<wmma::matrix_b, 16, 16, 16, half, wmma::col_major> HB;
typedef wmma::fragment<wmma::accumulator, 16, 16, 16, float> HCf;
typedef wmma::fragment<wmma::accumulator, 16, 16, 16, half>  HCh;

__device__ __forceinline__ void store_relu_half(half* dst, int ld, HCf& cf) {
    HCh ch;
#pragma unroll
    for (int i = 0; i < cf.num_elements; ++i)
        ch.x[i] = __float2half_rn(fmaxf(cf.x[i], 0.f));
    wmma::store_matrix_sync(dst, ch, ld, wmma::mem_row_major);
}

__global__ __launch_bounds__(256, 2) void l1234_kernel(
    const float* __restrict__ x,
    const float* __restrict__ w1, const float* __restrict__ w2,
    const float* __restrict__ w3, const float* __restrict__ w4) {
    extern __shared__ half hsm[];
    half* hb   = hsm;                        // 160*136 = 21760 h (h1, then h3)
    half* h2b  = hb + LROWS * HBLD;          // 160*72  = 11520 h (h2 / h4-chunk)
    half* wbuf = h2b + LROWS * H2LD2;        // 9216 h  (W2/W3/W4-chunk)
    __shared__ float W1t[CIN * C1];
    __shared__ float s_nbr[LPTS][KNN][3];
    __shared__ float s_dist[LPTS][KNN];
    __shared__ float s_xn[LPTS][3];

    const int tid = threadIdx.x, warp = tid >> 5;
    const size_t pt0 = (size_t)blockIdx.x * LPTS;

    // stage W1 (float, [c][o]); W2 (half, [o][c] ld 72)
    for (int i = tid; i < CIN * C1; i += 256) { int o = i / CIN, c = i % CIN; W1t[c * C1 + o] = w1[i]; }
    for (int i = tid; i < C2 * C2;  i += 256) { int o = i >> 6, c = i & 63; wbuf[o * H2LD2 + c] = __float2half_rn(w2[i]); }

    // gather neighbors + dist
    if (tid < LPTS * KNN) {
        int p = tid / KNN, k = tid % KNN;
        size_t pt = pt0 + p;
        int b = (int)(pt >> 12), n = (int)(pt & (NPTS - 1));
        const float* xb = x + (size_t)b * 3 * NPTS;
        int nb = g_idx[pt * KNN + k];
        float c0 = xb[n], c1 = xb[NPTS + n], c2 = xb[2 * NPTS + n];
        float n0 = xb[nb], n1 = xb[NPTS + nb], n2 = xb[2 * NPTS + nb];
        s_nbr[p][k][0] = n0; s_nbr[p][k][1] = n1; s_nbr[p][k][2] = n2;
        float d0 = n0 - c0, d1 = n1 - c1, d2 = n2 - c2;
        s_dist[p][k] = sqrtf(fmaf(d0, d0, fmaf(d1, d1, d2 * d2)) + 1e-12f);
        if (k < 3) s_xn[p][k] = xb[k * NPTS + n];
    }
    __syncthreads();

    // ---- L1 scalar: h1 rows -> hb (half), x1 -> cat[0:64] ----
    {
        int o = tid & 63;
#pragma unroll
        for (int pi = 0; pi < 2; ++pi) {
            int p = (tid >> 6) + pi * 4;
            float base = 0.f;
#pragma unroll
            for (int d = 0; d < 3; ++d) base = fmaf(W1t[d * C1 + o], s_xn[p][d], base);
#pragma unroll
            for (int j = 0; j < KNN; ++j) base = fmaf(W1t[(6 + j) * C1 + o], s_dist[p][j], base);
            float wa = W1t[3 * C1 + o], wb = W1t[4 * C1 + o], wc = W1t[5 * C1 + o];
            float mx = 0.f;
#pragma unroll
            for (int k = 0; k < KNN; ++k) {
                float v = fmaf(wa, s_nbr[p][k][0], fmaf(wb, s_nbr[p][k][1], fmaf(wc, s_nbr[p][k][2], base)));
                v = fmaxf(v, 0.f);
                mx = fmaxf(mx, v);
                hb[(p * KNN + k) * HBLD + o] = __float2half_rn(v);
            }
            g_cat[(pt0 + p) * CCAT + o] = mx;
        }
    }
    __syncthreads();

    // ---- L2: h2 = h1 @ W2^T : M=160, N=64 (40 tiles), K=64 -> h2b ----
    {
        HA fa; HB fb; HCf fc;
        for (int t = warp; t < 40; t += 8) {
            int mt = t >> 2, nt = t & 3;
            wmma::fill_fragment(fc, 0.f);
#pragma unroll
            for (int kt = 0; kt < 4; ++kt) {
                wmma::load_matrix_sync(fa, hb + mt * 16 * HBLD + kt * 16, HBLD);
                wmma::load_matrix_sync(fb, wbuf + nt * 16 * H2LD2 + kt * 16, H2LD2);
                wmma::mma_sync(fc, fa, fb, fc);
            }
            store_relu_half(h2b + mt * 16 * H2LD2 + nt * 16, H2LD2, fc);
        }
    }
    __syncthreads();

    // x2 -> cat[64:128]
    {
        int o = tid & 63;
#pragma unroll
        for (int pi = 0; pi < 2; ++pi) {
            int p = (tid >> 6) + pi * 4;
            float mx = 0.f;
#pragma unroll
            for (int k = 0; k < KNN; ++k)
                mx = fmaxf(mx, __half2float(h2b[(p * KNN + k) * H2LD2 + o]));
            g_cat[(pt0 + p) * CCAT + 64 + o] = mx;
        }
    }
    __syncthreads();

    // stage W3 (half, [o][c] ld 72)
    for (int i = tid; i < C3 * C2; i += 256) { int o = i >> 6, c = i & 63; wbuf[o * H2LD2 + c] = __float2half_rn(w3[i]); }
    __syncthreads();

    // ---- L3: h3 = h2 @ W3^T : M=160, N=128 (80 tiles), K=64 -> hb ----
    {
        HA fa; HB fb; HCf fc;
        for (int t = warp; t < 80; t += 8) {
            int mt = t >> 3, nt = t & 7;
            wmma::fill_fragment(fc, 0.f);
#pragma unroll
            for (int kt = 0; kt < 4; ++kt) {
                wmma::load_matrix_sync(fa, h2b + mt * 16 * H2LD2 + kt * 16, H2LD2);
                wmma::load_matrix_sync(fb, wbuf + nt * 16 * H2LD2 + kt * 16, H2LD2);
                wmma::mma_sync(fc, fa, fb, fc);
            }
            store_relu_half(hb + mt * 16 * HBLD + nt * 16, HBLD, fc);
        }
    }
    __syncthreads();

    // x3 -> cat[128:256]
    {
        int oc = tid & 127;
#pragma unroll
        for (int pi = 0; pi < 4; ++pi) {
            int p = (tid >> 7) + pi * 2;
            float mx = 0.f;
#pragma unroll
            for (int r = 0; r < KNN; ++r)
                mx = fmaxf(mx, __half2float(hb[(p * KNN + r) * HBLD + oc]));
            g_cat[(pt0 + p) * CCAT + 128 + oc] = mx;
        }
    }
    __syncthreads();

    // ---- L4: D2 = h3 @ W4^T : M=160, N=256 (4 chunks of 64), K=128 ----
    for (int co = 0; co < 4; ++co) {
        for (int i = tid; i < 64 * 128; i += 256) {
            int o = i >> 7, k = i & 127;
            wbuf[o * HBLD + k] = __float2half_rn(w4[(size_t)(co * 64 + o) * 128 + k]);
        }
        __syncthreads();
        {
            HA fa; HB fb; HCf fc;
            for (int t = warp; t < 40; t += 8) {
                int mt = t >> 2, nt = t & 3;
                wmma::fill_fragment(fc, 0.f);
#pragma unroll
                for (int kt = 0; kt < 8; ++kt) {
                    wmma::load_matrix_sync(fa, hb + mt * 16 * HBLD + kt * 16, HBLD);
                    wmma::load_matrix_sync(fb, wbuf + nt * 16 * HBLD + kt * 16, HBLD);
                    wmma::mma_sync(fc, fa, fb, fc);
                }
                store_relu_half(h2b + mt * 16 * H2LD2 + nt * 16, H2LD2, fc);
            }
        }
        __syncthreads();
        {   // x4 for this 64-oc chunk
            int o = tid & 63;
#pragma unroll
            for (int pi = 0; pi < 2; ++pi) {
                int p = (tid >> 6) + pi * 4;
                float mx = 0.f;
#pragma unroll
                for (int r = 0; r < KNN; ++r)
                    mx = fmaxf(mx, __half2float(h2b[(p * KNN + r) * H2LD2 + o]));
                g_cat[(pt0 + p) * CCAT + 256 + co * 64 + o] = mx;
            }
        }
        __syncthreads();
    }
}

// ===================== Kernel 3: L5 tiled GEMM (wmma fp16) =====================
#define KC5   64
#define ALD5  72                  // halves
#define TILEH (128 * ALD5)        // halves per tile buffer (9216)

__global__ __launch_bounds__(256, 2) void l5_kernel(
    const float* __restrict__ w5, float* __restrict__ out) {
    extern __shared__ half hsm[];
    half* bufA[2] = { hsm,         hsm + 2 * TILEH };
    half* bufB[2] = { hsm + TILEH, hsm + 3 * TILEH };

    const int tid = threadIdx.x, warp = tid >> 5;
    const int n0 = blockIdx.x * 128;
    const int o0 = blockIdx.y * 128;
    const int b  = blockIdx.z;
    const float* catg = g_cat + ((size_t)b * NPTS + n0) * CCAT;
    const float* wg   = w5 + (size_t)o0 * CCAT;
    const int wr = warp >> 2, wc = warp & 3;

    HCf fc[4][2];
#pragma unroll
    for (int i = 0; i < 4; ++i) { wmma::fill_fragment(fc[i][0], 0.f); wmma::fill_fragment(fc[i][1], 0.f); }

    auto stage = [&](int kc, int bi) {
        half* pa = bufA[bi]; half* pb = bufB[bi];
#pragma unroll
        for (int it = 0; it < 8; ++it) {
            int lin = tid + it * 256;
            int r = lin >> 4, q = lin & 15;
            float4 a = *(const float4*)(wg   + (size_t)r * CCAT + kc * KC5 + q * 4);
            float4 c = *(const float4*)(catg + (size_t)r * CCAT + kc * KC5 + q * 4);
            *(half2*)(pa + r * ALD5 + q * 4)     = __floats2half2_rn(a.x, a.y);
            *(half2*)(pa + r * ALD5 + q * 4 + 2) = __floats2half2_rn(a.z, a.w);
            *(half2*)(pb + r * ALD5 + q * 4)     = __floats2half2_rn(c.x, c.y);
            *(half2*)(pb + r * ALD5 + q * 4 + 2) = __floats2half2_rn(c.z, c.w);
        }
    };

    stage(0, 0);
    __syncthreads();

    HA fa; HB fb;
    for (int kc = 0; kc < 8; ++kc) {
        const int cur = kc & 1;
        if (kc + 1 < 8) stage(kc + 1, cur ^ 1);
        const half* A = bufA[cur];
        const half* B = bufB[cur];
#pragma unroll
        for (int kt = 0; kt < 4; ++kt) {
#pragma unroll
            for (int j = 0; j < 2; ++j) {
                wmma::load_matrix_sync(fb, B + (wc * 32 + j * 16) * ALD5 + kt * 16, ALD5);
#pragma unroll
                for (int i = 0; i < 4; ++i) {
                    wmma::load_matrix_sync(fa, A + (wr * 64 + i * 16) * ALD5 + kt * 16, ALD5);
                    wmma::mma_sync(fc[i][j], fa, fb, fc[i][j]);
                }
            }
        }
        __syncthreads();
    }

    float* scratch = (float*)hsm;   // 128*132*4 = 67584 <= 73728
#pragma unroll
    for (int i = 0; i < 4; ++i)
#pragma unroll
        for (int j = 0; j < 2; ++j)
            wmma::store_matrix_sync(scratch + (wr * 64 + i * 16) * 132 + wc * 32 + j * 16,
                                    fc[i][j], 132, wmma::mem_row_major);
    __syncthreads();

    for (int i = tid; i < 128 * 128; i += 256) {
        int o = i >> 7, n = i & 127;
        out[((size_t)b * EMB + o0 + o) * NPTS + n0 + n] = fmaxf(scratch[o * 132 + n], 0.f);
    }
}

// ===================== launch =====================
extern "C" void kernel_launch(void* const* d_in, const int* in_sizes, int n_in,
                              void* d_out, int out_size) {
    const float* x  = (const float*)d_in[0];
    const float* w1 = (const float*)d_in[1];
    const float* w2 = (const float*)d_in[2];
    const float* w3 = (const float*)d_in[3];
    const float* w4 = (const float*)d_in[4];
    const float* w5 = (const float*)d_in[5];
    float* out = (float*)d_out;

    const int knn_smem   = NPTS * sizeof(float4);                                    // 64 KB
    const int l1234_smem = (LROWS * HBLD + LROWS * H2LD2 + 128 * H2LD2) * sizeof(half); // 84992 B
    const int l5_smem    = 4 * TILEH * sizeof(half);                                 // 73728 B
    cudaFuncSetAttribute(knn_kernel,   cudaFuncAttributeMaxDynamicSharedMemorySize, knn_smem);
    cudaFuncSetAttribute(l1234_kernel, cudaFuncAttributeMaxDynamicSharedMemorySize, l1234_smem);
    cudaFuncSetAttribute(l5_kernel,    cudaFuncAttributeMaxDynamicSharedMemorySize, l5_smem);

    knn_kernel<<<dim3(NPTS / 64, BATCH), 256, knn_smem>>>(x);
    l1234_kernel<<<(BATCH * NPTS) / LPTS, 256, l1234_smem>>>(x, w1, w2, w3, w4);
    l5_kernel<<<dim3(NPTS / 128, EMB / 128, BATCH), 256, l5_smem>>>(w5, out);
}

// round 8
// speedup vs baseline: 3.2616x; 1.1414x over previous
#include <cuda_runtime.h>
#include <math_constants.h>
#include <mma.h>
#include <cuda_fp16.h>
#include <cstdint>

using namespace nvcuda;

#define BATCH 8
#define NPTS  4096
#define KNN   20
#define CIN   26
#define C1    64
#define C2    64
#define C3    128
#define C4    256
#define CCAT  512
#define EMB   512

__device__ int   g_idx[BATCH * NPTS * KNN];
__device__ float g_cat[(size_t)BATCH * NPTS * CCAT];     // 64 MB

// ===================== Kernel 1: exact 20-NN, 2 threads/point =====================
// Thread c scans candidates [c*2048, (c+1)*2048). Lexicographic merge preserves
// jax.lax.top_k ordering (ascending v, ties -> lower index).
__global__ __launch_bounds__(256) void knn_kernel(const float* __restrict__ x) {
    extern __shared__ float4 xs[];          // 4096*16 = 64KB
    __shared__ float mv[128][KNN];
    __shared__ int   mi[128][KNN];
    const int b = blockIdx.y;
    const float* xb = x + (size_t)b * 3 * NPTS;
    for (int m = threadIdx.x; m < NPTS; m += 256) {
        float x0 = xb[m], x1 = xb[NPTS + m], x2 = xb[2 * NPTS + m];
        xs[m] = make_float4(x0, x1, x2, fmaf(x0, x0, fmaf(x1, x1, x2 * x2)));
    }
    __syncthreads();
    const int lp = threadIdx.x >> 1;        // local point 0..127
    const int c  = threadIdx.x & 1;         // half 0..1
    const int n  = blockIdx.x * 128 + lp;
    float4 p = xs[n];
    const float a0 = -2.f * p.x, a1 = -2.f * p.y, a2 = -2.f * p.z;
    float bv[KNN]; int bi[KNN];
#pragma unroll
    for (int t = 0; t < KNN; ++t) { bv[t] = CUDART_INF_F; bi[t] = 0x7FFFFFFF; }
    const int m0 = c * 2048;
#pragma unroll 4
    for (int mm = 0; mm < 2048; ++mm) {
        int m = m0 + mm;
        float4 q = xs[m];
        float v = fmaf(a0, q.x, fmaf(a1, q.y, fmaf(a2, q.z, q.w)));
        if (v < bv[KNN - 1]) {
            bool ins = true;
#pragma unroll
            for (int t = KNN - 1; t >= 1; --t) {
                bool sh = v < bv[t - 1];
                if (sh)       { bv[t] = bv[t - 1]; bi[t] = bi[t - 1]; }
                else if (ins) { bv[t] = v;         bi[t] = m; }
                ins = sh;
            }
            if (ins) { bv[0] = v; bi[0] = m; }
        }
    }
    if (c == 1) {
#pragma unroll
        for (int t = 0; t < KNN; ++t) { mv[lp][t] = bv[t]; mi[lp][t] = bi[t]; }
    }
    __syncthreads();
    if (c == 0) {
#pragma unroll
        for (int e = 0; e < KNN; ++e) {
            float v = mv[lp][e]; int i = mi[lp][e];
            if (v < bv[KNN - 1] || (v == bv[KNN - 1] && i < bi[KNN - 1])) {
                bool ins = true;
#pragma unroll
                for (int t = KNN - 1; t >= 1; --t) {
                    bool sh = (v < bv[t - 1]) || (v == bv[t - 1] && i < bi[t - 1]);
                    if (sh)       { bv[t] = bv[t - 1]; bi[t] = bi[t - 1]; }
                    else if (ins) { bv[t] = v;         bi[t] = i; }
                    ins = sh;
                }
                if (ins) { bv[0] = v; bi[0] = i; }
            } else break;   // merge input is sorted: first failure ends merge
        }
        int* outp = g_idx + ((size_t)b * NPTS + n) * KNN;
#pragma unroll
        for (int t = 0; t < KNN; ++t) outp[t] = bi[t];
    }
}

// ===================== Kernel 2: fused L1(scalar) + L2/L3/L4 (wmma fp16) =====================
#define LPTS 8
#define LROWS (LPTS * KNN)   // 160
#define HBLD 136             // halves
#define H2LD2 72             // halves

typedef wmma::fragment<wmma::matrix_a, 16, 16, 16, half, wmma::row_major> HA;
typedef wmma::fragment<wmma::matrix_b, 16, 16, 16, half, wmma::col_major> HB;
typedef wmma::fragment<wmma::accumulator, 16, 16, 16, float> HCf;
typedef wmma::fragment<wmma::accumulator, 16, 16, 16, half>  HCh;

__device__ __forceinline__ void store_relu_half(half* dst, int ld, HCf& cf) {
    HCh ch;
#pragma unroll
    for (int i = 0; i < cf.num_elements; ++i)
        ch.x[i] = __float2half_rn(fmaxf(cf.x[i], 0.f));
    wmma::store_matrix_sync(dst, ch, ld, wmma::mem_row_major);
}

__global__ __launch_bounds__(256, 2) void l1234_kernel(
    const float* __restrict__ x,
    const float* __restrict__ w1, const float* __restrict__ w2,
    const float* __restrict__ w3, const float* __restrict__ w4) {
    extern __shared__ half hsm[];
    half* hb   = hsm;                        // 160*136 (h1, then h3)
    half* h2b  = hb + LROWS * HBLD;          // 160*72 (h2 / h4-chunk)
    half* wbuf = h2b + LROWS * H2LD2;        // 9216 h (W2/W3/W4-chunk)
    __shared__ float W1t[CIN * C1];
    __shared__ float s_nbr[LPTS][KNN][3];
    __shared__ float s_dist[LPTS][KNN];
    __shared__ float s_xn[LPTS][3];

    const int tid = threadIdx.x, warp = tid >> 5;
    const size_t pt0 = (size_t)blockIdx.x * LPTS;

    for (int i = tid; i < CIN * C1; i += 256) { int o = i / CIN, c = i % CIN; W1t[c * C1 + o] = w1[i]; }
    for (int i = tid; i < C2 * C2;  i += 256) { int o = i >> 6, c = i & 63; wbuf[o * H2LD2 + c] = __float2half_rn(w2[i]); }

    if (tid < LPTS * KNN) {
        int p = tid / KNN, k = tid % KNN;
        size_t pt = pt0 + p;
        int b = (int)(pt >> 12), n = (int)(pt & (NPTS - 1));
        const float* xb = x + (size_t)b * 3 * NPTS;
        int nb = g_idx[pt * KNN + k];
        float c0 = xb[n], c1 = xb[NPTS + n], c2 = xb[2 * NPTS + n];
        float n0 = xb[nb], n1 = xb[NPTS + nb], n2 = xb[2 * NPTS + nb];
        s_nbr[p][k][0] = n0; s_nbr[p][k][1] = n1; s_nbr[p][k][2] = n2;
        float d0 = n0 - c0, d1 = n1 - c1, d2 = n2 - c2;
        s_dist[p][k] = sqrtf(fmaf(d0, d0, fmaf(d1, d1, d2 * d2)) + 1e-12f);
        if (k < 3) s_xn[p][k] = xb[k * NPTS + n];
    }
    __syncthreads();

    // L1 scalar -> hb (half), x1 -> cat[0:64]
    {
        int o = tid & 63;
#pragma unroll
        for (int pi = 0; pi < 2; ++pi) {
            int p = (tid >> 6) + pi * 4;
            float base = 0.f;
#pragma unroll
            for (int d = 0; d < 3; ++d) base = fmaf(W1t[d * C1 + o], s_xn[p][d], base);
#pragma unroll
            for (int j = 0; j < KNN; ++j) base = fmaf(W1t[(6 + j) * C1 + o], s_dist[p][j], base);
            float wa = W1t[3 * C1 + o], wb = W1t[4 * C1 + o], wc = W1t[5 * C1 + o];
            float mx = 0.f;
#pragma unroll
            for (int k = 0; k < KNN; ++k) {
                float v = fmaf(wa, s_nbr[p][k][0], fmaf(wb, s_nbr[p][k][1], fmaf(wc, s_nbr[p][k][2], base)));
                v = fmaxf(v, 0.f);
                mx = fmaxf(mx, v);
                hb[(p * KNN + k) * HBLD + o] = __float2half_rn(v);
            }
            g_cat[(pt0 + p) * CCAT + o] = mx;
        }
    }
    __syncthreads();

    // L2: M=160,N=64,K=64 -> h2b
    {
        HA fa; HB fb; HCf fc;
        for (int t = warp; t < 40; t += 8) {
            int mt = t >> 2, nt = t & 3;
            wmma::fill_fragment(fc, 0.f);
#pragma unroll
            for (int kt = 0; kt < 4; ++kt) {
                wmma::load_matrix_sync(fa, hb + mt * 16 * HBLD + kt * 16, HBLD);
                wmma::load_matrix_sync(fb, wbuf + nt * 16 * H2LD2 + kt * 16, H2LD2);
                wmma::mma_sync(fc, fa, fb, fc);
            }
            store_relu_half(h2b + mt * 16 * H2LD2 + nt * 16, H2LD2, fc);
        }
    }
    __syncthreads();

    // x2 -> cat[64:128]
    {
        int o = tid & 63;
#pragma unroll
        for (int pi = 0; pi < 2; ++pi) {
            int p = (tid >> 6) + pi * 4;
            float mx = 0.f;
#pragma unroll
            for (int k = 0; k < KNN; ++k)
                mx = fmaxf(mx, __half2float(h2b[(p * KNN + k) * H2LD2 + o]));
            g_cat[(pt0 + p) * CCAT + 64 + o] = mx;
        }
    }
    __syncthreads();

    for (int i = tid; i < C3 * C2; i += 256) { int o = i >> 6, c = i & 63; wbuf[o * H2LD2 + c] = __float2half_rn(w3[i]); }
    __syncthreads();

    // L3: M=160,N=128,K=64 -> hb
    {
        HA fa; HB fb; HCf fc;
        for (int t = warp; t < 80; t += 8) {
            int mt = t >> 3, nt = t & 7;
            wmma::fill_fragment(fc, 0.f);
#pragma unroll
            for (int kt = 0; kt < 4; ++kt) {
                wmma::load_matrix_sync(fa, h2b + mt * 16 * H2LD2 + kt * 16, H2LD2);
                wmma::load_matrix_sync(fb, wbuf + nt * 16 * H2LD2 + kt * 16, H2LD2);
                wmma::mma_sync(fc, fa, fb, fc);
            }
            store_relu_half(hb + mt * 16 * HBLD + nt * 16, HBLD, fc);
        }
    }
    __syncthreads();

    // x3 -> cat[128:256]
    {
        int oc = tid & 127;
#pragma unroll
        for (int pi = 0; pi < 4; ++pi) {
            int p = (tid >> 7) + pi * 2;
            float mx = 0.f;
#pragma unroll
            for (int r = 0; r < KNN; ++r)
                mx = fmaxf(mx, __half2float(hb[(p * KNN + r) * HBLD + oc]));
            g_cat[(pt0 + p) * CCAT + 128 + oc] = mx;
        }
    }
    __syncthreads();

    // L4: M=160,N=256(4x64),K=128
    for (int co = 0; co < 4; ++co) {
        for (int i = tid; i < 64 * 128; i += 256) {
            int o = i >> 7, k = i & 127;
            wbuf[o * HBLD + k] = __float2half_rn(w4[(size_t)(co * 64 + o) * 128 + k]);
        }
        __syncthreads();
        {
            HA fa; HB fb; HCf fc;
            for (int t = warp; t < 40; t += 8) {
                int mt = t >> 2, nt = t & 3;
                wmma::fill_fragment(fc, 0.f);
#pragma unroll
                for (int kt = 0; kt < 8; ++kt) {
                    wmma::load_matrix_sync(fa, hb + mt * 16 * HBLD + kt * 16, HBLD);
                    wmma::load_matrix_sync(fb, wbuf + nt * 16 * HBLD + kt * 16, HBLD);
                    wmma::mma_sync(fc, fa, fb, fc);
                }
                store_relu_half(h2b + mt * 16 * H2LD2 + nt * 16, H2LD2, fc);
            }
        }
        __syncthreads();
        {
            int o = tid & 63;
#pragma unroll
            for (int pi = 0; pi < 2; ++pi) {
                int p = (tid >> 6) + pi * 4;
                float mx = 0.f;
#pragma unroll
                for (int r = 0; r < KNN; ++r)
                    mx = fmaxf(mx, __half2float(h2b[(p * KNN + r) * H2LD2 + o]));
                g_cat[(pt0 + p) * CCAT + 256 + co * 64 + o] = mx;
            }
        }
        __syncthreads();
    }
}

// ===================== Kernel 3: L5 tiled GEMM (wmma fp16) =====================
#define KC5   64
#define ALD5  72
#define TILEH (128 * ALD5)

__global__ __launch_bounds__(256, 2) void l5_kernel(
    const float* __restrict__ w5, float* __restrict__ out) {
    extern __shared__ half hsm[];
    half* bufA[2] = { hsm,         hsm + 2 * TILEH };
    half* bufB[2] = { hsm + TILEH, hsm + 3 * TILEH };

    const int tid = threadIdx.x, warp = tid >> 5;
    const int n0 = blockIdx.x * 128;
    const int o0 = blockIdx.y * 128;
    const int b  = blockIdx.z;
    const float* catg = g_cat + ((size_t)b * NPTS + n0) * CCAT;
    const float* wg   = w5 + (size_t)o0 * CCAT;
    const int wr = warp >> 2, wc = warp & 3;

    HCf fc[4][2];
#pragma unroll
    for (int i = 0; i < 4; ++i) { wmma::fill_fragment(fc[i][0], 0.f); wmma::fill_fragment(fc[i][1], 0.f); }

    auto stage = [&](int kc, int bi) {
        half* pa = bufA[bi]; half* pb = bufB[bi];
#pragma unroll
        for (int it = 0; it < 8; ++it) {
            int lin = tid + it * 256;
            int r = lin >> 4, q = lin & 15;
            float4 a = *(const float4*)(wg   + (size_t)r * CCAT + kc * KC5 + q * 4);
            float4 c = *(const float4*)(catg + (size_t)r * CCAT + kc * KC5 + q * 4);
            *(half2*)(pa + r * ALD5 + q * 4)     = __floats2half2_rn(a.x, a.y);
            *(half2*)(pa + r * ALD5 + q * 4 + 2) = __floats2half2_rn(a.z, a.w);
            *(half2*)(pb + r * ALD5 + q * 4)     = __floats2half2_rn(c.x, c.y);
            *(half2*)(pb + r * ALD5 + q * 4 + 2) = __floats2half2_rn(c.z, c.w);
        }
    };

    stage(0, 0);
    __syncthreads();

    HA fa; HB fb;
    for (int kc = 0; kc < 8; ++kc) {
        const int cur = kc & 1;
        if (kc + 1 < 8) stage(kc + 1, cur ^ 1);
        const half* A = bufA[cur];
        const half* B = bufB[cur];
#pragma unroll
        for (int kt = 0; kt < 4; ++kt) {
#pragma unroll
            for (int j = 0; j < 2; ++j) {
                wmma::load_matrix_sync(fb, B + (wc * 32 + j * 16) * ALD5 + kt * 16, ALD5);
#pragma unroll
                for (int i = 0; i < 4; ++i) {
                    wmma::load_matrix_sync(fa, A + (wr * 64 + i * 16) * ALD5 + kt * 16, ALD5);
                    wmma::mma_sync(fc[i][j], fa, fb, fc[i][j]);
                }
            }
        }
        __syncthreads();
    }

    float* scratch = (float*)hsm;
#pragma unroll
    for (int i = 0; i < 4; ++i)
#pragma unroll
        for (int j = 0; j < 2; ++j)
            wmma::store_matrix_sync(scratch + (wr * 64 + i * 16) * 132 + wc * 32 + j * 16,
                                    fc[i][j], 132, wmma::mem_row_major);
    __syncthreads();

    for (int i = tid; i < 128 * 128; i += 256) {
        int o = i >> 7, n = i & 127;
        out[((size_t)b * EMB + o0 + o) * NPTS + n0 + n] = fmaxf(scratch[o * 132 + n], 0.f);
    }
}

// ===================== launch =====================
extern "C" void kernel_launch(void* const* d_in, const int* in_sizes, int n_in,
                              void* d_out, int out_size) {
    const float* x  = (const float*)d_in[0];
    const float* w1 = (const float*)d_in[1];
    const float* w2 = (const float*)d_in[2];
    const float* w3 = (const float*)d_in[3];
    const float* w4 = (const float*)d_in[4];
    const float* w5 = (const float*)d_in[5];
    float* out = (float*)d_out;

    const int knn_smem   = NPTS * sizeof(float4);                                       // 64 KB dyn
    const int l1234_smem = (LROWS * HBLD + LROWS * H2LD2 + 128 * H2LD2) * sizeof(half); // ~85 KB
    const int l5_smem    = 4 * TILEH * sizeof(half);                                    // 72 KB
    cudaFuncSetAttribute(knn_kernel,   cudaFuncAttributeMaxDynamicSharedMemorySize, knn_smem);
    cudaFuncSetAttribute(l1234_kernel, cudaFuncAttributeMaxDynamicSharedMemorySize, l1234_smem);
    cudaFuncSetAttribute(l5_kernel,    cudaFuncAttributeMaxDynamicSharedMemorySize, l5_smem);

    knn_kernel<<<dim3(NPTS / 128, BATCH), 256, knn_smem>>>(x);
    l1234_kernel<<<(BATCH * NPTS) / LPTS, 256, l1234_smem>>>(x, w1, w2, w3, w4);
    l5_kernel<<<dim3(NPTS / 128, EMB / 128, BATCH), 256, l5_smem>>>(w5, out);
}